// round 12
// baseline (speedup 1.0000x reference)
#include <cuda_runtime.h>
#include <cuda_bf16.h>
#include <math.h>

// ---------------- problem constants ----------------
#define NB     1025          // 1 + P*S sentences
#define NNODE  63
#define NROWS  (NB*NNODE)    // 64575
#define VOCAB  50000
#define IN_D   300
#define MDIM   300           // 2*mem_dim
#define MEMD   150
#define G3     900           // 3*M
#define NCX    1200          // 3M + M  (iou + f)
#define PP     32
#define SS     32

// ---------------- device scratch (static; no allocation APIs) ----------------
__device__ float g_xproj[VOCAB * NCX];        // 240 MB : per-UNIQUE-token [iou(900)|f(300)]
__device__ float g_h[NROWS * MDIM];           // tree h
__device__ float g_c[NROWS * MDIM];           // tree c
__device__ float g_g1[NB * 16 * G3];          // level GEMM: (c0+c1)@w_iouh^T
__device__ float g_g2[NB * 32 * MDIM];        // level GEMM: c_child@w_fh^T
__device__ float g_wx[NCX * IN_D];            // [w_ioux ; w_fx] combined
__device__ float g_biasx[NCX];
__device__ float g_bias_pf[600];
__device__ float g_bias_pr[600];
__device__ float g_bias_bd[600];
__device__ float g_xg_pf[1024 * 600];
__device__ float g_xg_pr[1024 * 600];
__device__ float g_ph[2 * 32 * MEMD];         // paragraph LSTM h state (fwd,rev)
__device__ float g_pc[2 * 32 * MEMD];
__device__ float g_phidden[32 * MDIM];        // concat(hT_f, hT_r)
__device__ float g_xg_bd[32 * 600];
__device__ float g_hbody[32 * MDIM];
__device__ float g_gatel[32 * MDIM];

// padded (stride-152, zero-filled) recurrent weights for float4 inner loops
__device__ float g_whh_pf_p[600 * 152];
__device__ float g_whh_pr_p[600 * 152];
__device__ float g_whh_bd_p[600 * 152];

// token dedup
__device__ int g_map[VOCAB];                  // tok -> winning row (claim phase)
__device__ int g_tokid[VOCAB];                // tok -> compact unique id
__device__ int g_utok[VOCAB];                 // unique id -> tok
__device__ int g_uid[NROWS];                  // row -> unique id
__device__ int g_cnt;

// ---------------- fast transcendentals (MUFU-based, ~1e-6 rel accuracy) --------
__device__ __forceinline__ float sigmf(float x)
{
    float xc = fminf(fmaxf(x, -15.f), 15.f);
    return __fdividef(1.f, 1.f + __expf(-xc));
}
__device__ __forceinline__ float tanhfast(float x)
{
    float xc = fminf(fmaxf(x, -15.f), 15.f);
    float e = __expf(2.f * xc);
    return __fdividef(e - 1.f, e + 1.f);
}

__device__ __forceinline__ int row_tok(int r, const int* __restrict__ headt,
                                       const int* __restrict__ bodyt)
{
    return (r < NNODE) ? headt[r] : bodyt[r - NNODE];
}

// ---------------- split-TF32 helpers ----------------
__device__ __forceinline__ void tf32_split(float v, float& hf, float& lf)
{
    unsigned h; asm("cvt.rna.tf32.f32 %0, %1;" : "=r"(h) : "f"(v));
    hf = __uint_as_float(h);
    float lo = v - hf;
    unsigned l; asm("cvt.rna.tf32.f32 %0, %1;" : "=r"(l) : "f"(lo));
    lf = __uint_as_float(l);
}

__device__ __forceinline__ void mma_tf32(float* d, const unsigned* a, const unsigned* b)
{
    asm volatile("mma.sync.aligned.m16n8k8.row.col.f32.tf32.tf32.f32 "
                 "{%0,%1,%2,%3}, {%4,%5,%6,%7}, {%8,%9}, {%0,%1,%2,%3};"
                 : "+f"(d[0]), "+f"(d[1]), "+f"(d[2]), "+f"(d[3])
                 : "r"(a[0]), "r"(a[1]), "r"(a[2]), "r"(a[3]),
                   "r"(b[0]), "r"(b[1]));
}

// ---------------- dedup pipeline ----------------
__global__ void dedup_claim(const int* __restrict__ headt, const int* __restrict__ bodyt)
{
    int r = blockIdx.x * 256 + threadIdx.x;
    if (r >= NROWS) return;
    atomicCAS(&g_map[row_tok(r, headt, bodyt)], -1, r);
}
__global__ void dedup_assign(const int* __restrict__ headt, const int* __restrict__ bodyt)
{
    int r = blockIdx.x * 256 + threadIdx.x;
    if (r >= NROWS) return;
    int tok = row_tok(r, headt, bodyt);
    if (g_map[tok] == r) {                    // winner allocates the compact id
        int id = atomicAdd(&g_cnt, 1);
        g_tokid[tok] = id;
        g_utok[id] = tok;
    }
}
__global__ void dedup_gather(const int* __restrict__ headt, const int* __restrict__ bodyt)
{
    int r = blockIdx.x * 256 + threadIdx.x;
    if (r >= NROWS) return;
    g_uid[r] = g_tokid[row_tok(r, headt, bodyt)];
}

// ---------------- prep: biases, combined x-weight, map init, padded whh -------
__global__ void prep_kernel(const float* __restrict__ b_ioux, const float* __restrict__ b_iouh,
                            const float* __restrict__ b_fx,
                            const float* __restrict__ b_ih_pf, const float* __restrict__ b_hh_pf,
                            const float* __restrict__ b_ih_pr, const float* __restrict__ b_hh_pr,
                            const float* __restrict__ b_ih_bd, const float* __restrict__ b_hh_bd,
                            const float* __restrict__ w_ioux, const float* __restrict__ w_fx,
                            const float* __restrict__ w_hh_pf, const float* __restrict__ w_hh_pr,
                            const float* __restrict__ w_hh_bd)
{
    int i = blockIdx.x * 256 + threadIdx.x;
    if (i < 900)            g_biasx[i] = b_ioux[i] + b_iouh[i];
    else if (i < 1200)      g_biasx[i] = b_fx[i - 900];
    else if (i < 1800)      { int q = i - 1200; g_bias_pf[q] = b_ih_pf[q] + b_hh_pf[q]; }
    else if (i < 2400)      { int q = i - 1800; g_bias_pr[q] = b_ih_pr[q] + b_hh_pr[q]; }
    else if (i < 3000)      { int q = i - 2400; g_bias_bd[q] = b_ih_bd[q] + b_hh_bd[q]; }
    else if (i < 273000)    { int q = i - 3000;   g_wx[q] = w_ioux[q]; }
    else if (i < 363000)    { int q = i - 273000; g_wx[270000 + q] = w_fx[q]; }
    else if (i < 413000)    { int q = i - 363000; g_map[q] = -1; if (q == 0) g_cnt = 0; }
    else if (i < 504200)    { int q = i - 413000; int r = q / 152, k = q - r * 152;
                              g_whh_pf_p[q] = (k < 150) ? w_hh_pf[r * 150 + k] : 0.f; }
    else if (i < 595400)    { int q = i - 504200; int r = q / 152, k = q - r * 152;
                              g_whh_pr_p[q] = (k < 150) ? w_hh_pr[r * 150 + k] : 0.f; }
    else if (i < 686600)    { int q = i - 595400; int r = q / 152, k = q - r * 152;
                              g_whh_bd_p[q] = (k < 150) ? w_hh_bd[r * 150 + k] : 0.f; }
}

// ---------------- generic K=300 GEMM:  C[r,n] = sum_k A(r,k) * W[n,k] + bias[n] ----
// MODE 0 : A(r,k) = emb[g_utok[r]*300+k], rows = g_cnt (dynamic, early-exit)
// MODE 4 : A(r,k) = A[r*300+k]          (plain)
// MODE 5 : MERGED para x-gate launch: blockIdx.y>=8 -> reverse job.
//          A(r,k) = c_root of sentence (row r = t*32+p, time-reversed for job 1);
//          W/bias/C selected per job (W=fwd, W2=rev; biases/outputs via symbols).
// MODE 12: MERGED tree-level launch. blockIdx.x<8 -> iou GEMM
//          (A = c[child0]+c[child1], W, C, ncols=900, rows);
//          blockIdx.x>=8 -> f GEMM (A = c[child], W2, C2, ncols=300, rows*2).
//
// TENSOR-CORE core: 128x128 CTA tile, 8 warps in 2x4 (64 rows x 32 cols each),
// split-TF32 mma.sync m16n8k8 (3 MMAs: hi*hi + hi*lo + lo*hi == fp32 accuracy).
// SMEM stores {hi,lo} INTERLEAVED per (row,k) with row stride 40 words:
// every fragment element is ONE conflict-free LDS.64 yielding both planes
// (24 LDS.64 per k8-step vs 48 LDS.32 before -> half the shared-pipe issue).
template<int MODE>
__global__ void __launch_bounds__(256, 2) gemm300(
    const float* __restrict__ A, const float* __restrict__ W,
    const float* __restrict__ bias, float* __restrict__ C,
    int rows, int ncols,
    const float* __restrict__ W2, float* __restrict__ C2,
    int size, int offPrev, int rev)
{
    __shared__ __align__(16) float As[128 * 40];   // (row,k) -> [row*40 + 2k] = hi, +1 = lo
    __shared__ __align__(16) float Bs[128 * 40];
    __shared__ int rbase[128];

    const int tid = threadIdx.x;

    bool m2 = false;
    int job = 0;
    int rowBase, colBase;
    const float* Wsel = W;
    float*       Csel = C;
    const float* biasE = bias;
    int ncolsE = ncols;
    int nrows;
    if (MODE == 12) {
        rowBase = blockIdx.y * 128;
        m2 = blockIdx.x >= 8;
        colBase = m2 ? (blockIdx.x - 8) * 128 : blockIdx.x * 128;
        Wsel = m2 ? W2 : W;
        Csel = m2 ? C2 : C;
        ncolsE = m2 ? MDIM : G3;
        nrows = m2 ? rows * 2 : rows;
    } else if (MODE == 5) {
        job = blockIdx.y >> 3;
        rowBase = (blockIdx.y & 7) * 128;
        colBase = blockIdx.x * 128;
        Wsel = job ? W2 : W;
        Csel = job ? g_xg_pr : g_xg_pf;
        biasE = job ? g_bias_pr : g_bias_pf;
        ncolsE = 600;
        nrows = 1024;
    } else {
        rowBase = blockIdx.y * 128;
        colBase = blockIdx.x * 128;
        nrows = (MODE == 0) ? g_cnt : rows;
    }
    if ((MODE == 0 || MODE == 12) && rowBase >= nrows) return;   // uniform per block

    if (tid < 128) {
        int r = rowBase + tid;
        int rb = -1;
        if (r < nrows) {
            if (MODE == 0)       { rb = g_utok[r] * 300; }
            else if (MODE == 12) {
                if (!m2) { int b = r / size; int kk = r - b * size;
                           rb = (b * NNODE + offPrev + 2 * kk) * MDIM; }
                else     { int s2 = size * 2; int b = r / s2; int rem = r - b * s2;
                           rb = (b * NNODE + offPrev + rem) * MDIM; }
            }
            else if (MODE == 5)  { int t = r >> 5, p = r & 31; int te = job ? 31 - t : t;
                                   rb = ((1 + p * 32 + te) * NNODE + 62) * MDIM; }
            else                 rb = r * 300;
        }
        rbase[tid] = rb;
    }
    __syncthreads();

    // loader mapping: 256 threads; each loads 2 A-rows and 2 W-rows, one float4 each
    const int lrow = tid >> 2;            // 0..63
    const int kq   = (tid & 3) * 4;       // k offset within 16-wide tile: 0,4,8,12
    const int arb0 = rbase[lrow];
    const int arb1 = rbase[lrow + 64];
    const int wr0  = colBase + lrow;
    const int wr1  = colBase + lrow + 64;
    const bool w0ok = wr0 < ncolsE;
    const bool w1ok = wr1 < ncolsE;
    const float* wp0 = Wsel + (size_t)(w0ok ? wr0 : 0) * 300;
    const float* wp1 = Wsel + (size_t)(w1ok ? wr1 : 0) * 300;

    // mma fragment mapping
    const int w    = tid >> 5, lane = tid & 31;
    const int g    = lane >> 2, t4 = lane & 3;
    const int wrr  = w & 1;               // 0..1 -> 64-row group
    const int wcc  = w >> 1;              // 0..3 -> 32-col group

    float c[4][4][4];                     // [mtile][ntile][reg], 64 accum regs
#pragma unroll
    for (int mt = 0; mt < 4; mt++)
#pragma unroll
        for (int nt = 0; nt < 4; nt++)
#pragma unroll
            for (int q = 0; q < 4; q++) c[mt][nt][q] = 0.f;

    float4 a0v, a1v, w0v, w1v;

    auto LOADT = [&](int k0) {
        const float4 Z = make_float4(0.f, 0.f, 0.f, 0.f);
        a0v = Z; a1v = Z; w0v = Z; w1v = Z;
        int k = k0 + kq;
        if (k < 300) {
            if (arb0 >= 0) {
                a0v = *(const float4*)(A + arb0 + k);
                if (MODE == 12 && !m2) {
                    float4 t2 = *(const float4*)(A + arb0 + 300 + k);
                    a0v.x += t2.x; a0v.y += t2.y; a0v.z += t2.z; a0v.w += t2.w;
                }
            }
            if (arb1 >= 0) {
                a1v = *(const float4*)(A + arb1 + k);
                if (MODE == 12 && !m2) {
                    float4 t2 = *(const float4*)(A + arb1 + 300 + k);
                    a1v.x += t2.x; a1v.y += t2.y; a1v.z += t2.z; a1v.w += t2.w;
                }
            }
            if (w0ok) w0v = *(const float4*)(wp0 + k);
            if (w1ok) w1v = *(const float4*)(wp1 + k);
        }
    };

    // store 4 k-values as interleaved {hi,lo} pairs: 8 words = 2 float4 stores
    auto SPLIT4I = [&](float4 v, float* p) {
        float4 h, l;
        tf32_split(v.x, h.x, l.x); tf32_split(v.y, h.y, l.y);
        tf32_split(v.z, h.z, l.z); tf32_split(v.w, h.w, l.w);
        *(float4*)p       = make_float4(h.x, l.x, h.y, l.y);
        *(float4*)(p + 4) = make_float4(h.z, l.z, h.w, l.w);
    };

    auto STORET = [&]() {
        int s0 = lrow * 40 + kq * 2;
        int s1 = (lrow + 64) * 40 + kq * 2;
        SPLIT4I(a0v, &As[s0]);
        SPLIT4I(a1v, &As[s1]);
        SPLIT4I(w0v, &Bs[s0]);
        SPLIT4I(w1v, &Bs[s1]);
    };

    LOADT(0);
    for (int k0 = 0; k0 < 300; k0 += 16) {
        STORET();
        __syncthreads();
        if (k0 + 16 < 300) LOADT(k0 + 16);    // prefetch hidden under the MMAs
#pragma unroll
        for (int ks = 0; ks < 2; ks++) {
            const int kb = ks * 8;
            unsigned bh[4][2], bl[4][2];
#pragma unroll
            for (int nt = 0; nt < 4; nt++) {
                int cb = (wcc * 32 + nt * 8 + g) * 40 + (kb + t4) * 2;
                uint2 b0 = *(const uint2*)&Bs[cb];
                uint2 b1 = *(const uint2*)&Bs[cb + 8];
                bh[nt][0] = b0.x; bh[nt][1] = b1.x;
                bl[nt][0] = b0.y; bl[nt][1] = b1.y;
            }
#pragma unroll
            for (int mt = 0; mt < 4; mt++) {
                int rb0 = (wrr * 64 + mt * 16 + g) * 40 + (kb + t4) * 2;
                int rb1 = rb0 + 8 * 40;
                uint2 a00 = *(const uint2*)&As[rb0];
                uint2 a10 = *(const uint2*)&As[rb1];
                uint2 a01 = *(const uint2*)&As[rb0 + 8];
                uint2 a11 = *(const uint2*)&As[rb1 + 8];
                unsigned ah[4] = { a00.x, a10.x, a01.x, a11.x };
                unsigned al[4] = { a00.y, a10.y, a01.y, a11.y };
#pragma unroll
                for (int nt = 0; nt < 4; nt++) {
                    mma_tf32(c[mt][nt], ah, bh[nt]);   // hi*hi
                    mma_tf32(c[mt][nt], ah, bl[nt]);   // hi*lo
                    mma_tf32(c[mt][nt], al, bh[nt]);   // lo*hi
                }
            }
        }
        __syncthreads();
    }

    // epilogue: c regs -> D rows (g, g+8), cols (2t, 2t+1). ncolsE is even, col
    // even -> float2 store in-bounds iff col < ncolsE. 8B-aligned.
#pragma unroll
    for (int mt = 0; mt < 4; mt++) {
        int r0 = rowBase + wrr * 64 + mt * 16 + g;
        int r1 = r0 + 8;
#pragma unroll
        for (int nt = 0; nt < 4; nt++) {
            int col = colBase + wcc * 32 + nt * 8 + 2 * t4;
            if (col >= ncolsE) continue;
            float bx = 0.f, by = 0.f;
            if (biasE) { float2 bv = *(const float2*)(biasE + col); bx = bv.x; by = bv.y; }
            if (r0 < nrows) {
                float2 v = make_float2(c[mt][nt][0] + bx, c[mt][nt][1] + by);
                *(float2*)(Csel + (size_t)r0 * ncolsE + col) = v;
            }
            if (r1 < nrows) {
                float2 v = make_float2(c[mt][nt][2] + bx, c[mt][nt][3] + by);
                *(float2*)(Csel + (size_t)r1 * ncolsE + col) = v;
            }
        }
    }
}

// ---------------- tree level 0 (leaves), float4-vectorized -----------------
__global__ void __launch_bounds__(256) leaf_kernel_f4(int total)   // total = NB*32*75
{
    int e = blockIdx.x * 256 + threadIdx.x;
    if (e >= total) return;
    int n = e / 75, q = e - n * 75;       // node index, float4 chunk
    int b = n >> 5, leaf = n & 31;
    int pos = b * NNODE + leaf;
    const float4* xr = (const float4*)(g_xproj + (size_t)g_uid[pos] * NCX);
    float4 iv = xr[q], ov = xr[75 + q], uv = xr[150 + q];
    float4 cv, hv;
    { float i = sigmf(iv.x), o = sigmf(ov.x), u = tanhfast(uv.x);
      cv.x = i * u; hv.x = o * tanhfast(cv.x); }
    { float i = sigmf(iv.y), o = sigmf(ov.y), u = tanhfast(uv.y);
      cv.y = i * u; hv.y = o * tanhfast(cv.y); }
    { float i = sigmf(iv.z), o = sigmf(ov.z), u = tanhfast(uv.z);
      cv.z = i * u; hv.z = o * tanhfast(cv.z); }
    { float i = sigmf(iv.w), o = sigmf(ov.w), u = tanhfast(uv.w);
      cv.w = i * u; hv.w = o * tanhfast(cv.w); }
    ((float4*)g_c)[(size_t)pos * 75 + q] = cv;
    ((float4*)g_h)[(size_t)pos * 75 + q] = hv;
}

// ---------------- tree levels 1..5, float4-vectorized ----------------------
__global__ void __launch_bounds__(256) node_kernel_f4(
    int size, int off, int offPrev, const float* __restrict__ b_fh, int total)
{
    int e = blockIdx.x * 256 + threadIdx.x;
    if (e >= total) return;               // total = NB*size*75
    int n = e / 75, q = e - n * 75;       // n = b*size+kk == grow
    int b = n / size, kk = n - b * size;
    int node = off + kk;
    int pos = b * NNODE + node;
    const float4* xr  = (const float4*)(g_xproj + (size_t)g_uid[pos] * NCX);
    const float4* g1r = (const float4*)(g_g1 + (size_t)n * G3);
    const float4* g2r = (const float4*)(g_g2 + (size_t)n * (2 * MDIM));
    int ch = offPrev + 2 * kk;
    const float4* h0 = (const float4*)g_h + (size_t)(b * NNODE + ch) * 75;

    float4 iv = xr[q],       ovv = xr[75 + q],  uvv = xr[150 + q], fxv = xr[225 + q];
    float4 g1a = g1r[q],     g1b = g1r[75 + q], g1c = g1r[150 + q];
    float4 g2a = g2r[q],     g2b = g2r[75 + q];
    float4 bf  = ((const float4*)b_fh)[q];
    float4 h0v = h0[q],      h1v = h0[75 + q];

    float4 cv, hv;
    { float i = sigmf(iv.x + g1a.x), o = sigmf(ovv.x + g1b.x), u = tanhfast(uvv.x + g1c.x);
      float fx = fxv.x + bf.x;
      float f0 = sigmf(g2a.x + fx), f1 = sigmf(g2b.x + fx);
      cv.x = i * u + f0 * h0v.x + f1 * h1v.x; hv.x = o * tanhfast(cv.x); }
    { float i = sigmf(iv.y + g1a.y), o = sigmf(ovv.y + g1b.y), u = tanhfast(uvv.y + g1c.y);
      float fx = fxv.y + bf.y;
      float f0 = sigmf(g2a.y + fx), f1 = sigmf(g2b.y + fx);
      cv.y = i * u + f0 * h0v.y + f1 * h1v.y; hv.y = o * tanhfast(cv.y); }
    { float i = sigmf(iv.z + g1a.z), o = sigmf(ovv.z + g1b.z), u = tanhfast(uvv.z + g1c.z);
      float fx = fxv.z + bf.z;
      float f0 = sigmf(g2a.z + fx), f1 = sigmf(g2b.z + fx);
      cv.z = i * u + f0 * h0v.z + f1 * h1v.z; hv.z = o * tanhfast(cv.z); }
    { float i = sigmf(iv.w + g1a.w), o = sigmf(ovv.w + g1b.w), u = tanhfast(uvv.w + g1c.w);
      float fx = fxv.w + bf.w;
      float f0 = sigmf(g2a.w + fx), f1 = sigmf(g2b.w + fx);
      cv.w = i * u + f0 * h0v.w + f1 * h1v.w; hv.w = o * tanhfast(cv.w); }
    ((float4*)g_c)[(size_t)pos * 75 + q] = cv;
    ((float4*)g_h)[(size_t)pos * 75 + q] = hv;
}

// ---------------- paragraph bi-LSTM: ALL 32 steps in one launch ----------------
__global__ void para_all()
{
    int job = blockIdx.y;                // 0 = fwd, 1 = rev
    int pb = blockIdx.x * 4;
    const float* xg  = job ? g_xg_pr : g_xg_pf;
    const float* whp = job ? g_whh_pr_p : g_whh_pf_p;
    float* hs = g_ph + job * 32 * MEMD;
    float* cs = g_pc + job * 32 * MEMD;
    __shared__ __align__(16) float hsh[608];   // 4 regions x 152 (pads zeroed)
    __shared__ float gsh[2400];                // 4 x 600
    int j = threadIdx.x;                       // 600
    if (j < 8) { int r = j >> 1; hsh[r * 152 + 150 + (j & 1)] = 0.f; }
    const float4* wr4 = (const float4*)(whp + (size_t)j * 152);
    for (int t = 0; t < 32; t++) {
        if (t > 0) { int pp = j / MEMD, m = j % MEMD;
                     hsh[pp * 152 + m] = hs[(pb + pp) * MEMD + m]; }
        __syncthreads();

        int xb = ((t << 5) + pb) * 600 + j;
        float a0 = xg[xb], a1 = xg[xb + 600], a2 = xg[xb + 1200], a3 = xg[xb + 1800];
        if (t > 0) {
#pragma unroll 19
            for (int k4 = 0; k4 < 38; k4++) {
                float4 w  = wr4[k4];
                float4 h0 = *(const float4*)&hsh[k4 * 4];
                float4 h1 = *(const float4*)&hsh[152 + k4 * 4];
                float4 h2 = *(const float4*)&hsh[304 + k4 * 4];
                float4 h3 = *(const float4*)&hsh[456 + k4 * 4];
                a0 += w.x * h0.x + w.y * h0.y + w.z * h0.z + w.w * h0.w;
                a1 += w.x * h1.x + w.y * h1.y + w.z * h1.z + w.w * h1.w;
                a2 += w.x * h2.x + w.y * h2.y + w.z * h2.z + w.w * h2.w;
                a3 += w.x * h3.x + w.y * h3.y + w.z * h3.z + w.w * h3.w;
            }
        }
        gsh[j] = a0; gsh[600 + j] = a1; gsh[1200 + j] = a2; gsh[1800 + j] = a3;
        __syncthreads();

        int pp = j / MEMD, m = j % MEMD;
        int p = pb + pp;
        const float* gp = gsh + pp * 600;
        float gi = gp[m], gf = gp[150 + m], gg = gp[300 + m], go = gp[450 + m];
        float cprev = (t > 0) ? cs[p * MEMD + m] : 0.f;
        float c2 = sigmf(gf) * cprev + sigmf(gi) * tanhfast(gg);
        float h2 = sigmf(go) * tanhfast(c2);
        cs[p * MEMD + m] = c2;
        hs[p * MEMD + m] = h2;
        if (t == 31) g_phidden[p * MDIM + job * MEMD + m] = h2;
        __syncthreads();                 // h/c writes visible before next t's hsh load
    }
}

// ---------------- body LSTM scan (upstream quirk: bwd cell uses fresh fwd h) ---
__global__ void body_scan()
{
    __shared__ __align__(16) float hf[152];
    __shared__ float cf[MEMD], cb[MEMD], g[600];
    int j = threadIdx.x;                 // 600
    if (j < 2) hf[150 + j] = 0.f;        // pad
    const float4* wr4 = (const float4*)(g_whh_bd_p + (size_t)j * 152);
    __syncthreads();
    for (int t = 0; t < 32; t++) {
        float acc = g_xg_bd[t * 600 + j];
        if (t > 0) {
#pragma unroll 19
            for (int k4 = 0; k4 < 38; k4++) {
                float4 w = wr4[k4];
                float4 h = *(const float4*)&hf[k4 * 4];
                acc += w.x * h.x + w.y * h.y + w.z * h.z + w.w * h.w;
            }
        }
        g[j] = acc;
        __syncthreads();
        if (j < MEMD) {
            float cprev = (t > 0) ? cf[j] : 0.f;
            float c2 = sigmf(g[150 + j]) * cprev + sigmf(g[j]) * tanhfast(g[300 + j]);
            float h2 = sigmf(g[450 + j]) * tanhfast(c2);
            cf[j] = c2; hf[j] = h2;
            g_hbody[t * MDIM + j] = h2;
        }
        __syncthreads();
        float acc2 = g_xg_bd[(31 - t) * 600 + j];
        {
#pragma unroll 19
            for (int k4 = 0; k4 < 38; k4++) {
                float4 w = wr4[k4];
                float4 h = *(const float4*)&hf[k4 * 4];   // hf == fresh h_f2
                acc2 += w.x * h.x + w.y * h.y + w.z * h.z + w.w * h.w;
            }
        }
        g[j] = acc2;
        __syncthreads();
        if (j < MEMD) {
            float cprev = (t > 0) ? cb[j] : 0.f;
            float c2 = sigmf(g[150 + j]) * cprev + sigmf(g[j]) * tanhfast(g[300 + j]);
            float h2 = sigmf(g[450 + j]) * tanhfast(c2);
            cb[j] = c2;
            g_hbody[t * MDIM + 150 + j] = h2;
        }
        __syncthreads();
    }
}

// ---------------- gating: logits[p,m] = w_sel[m,:] . [h_body[p] ; para_rep] ----
__global__ void gate_logits(const float* __restrict__ w_sel, const float* __restrict__ b_sel)
{
    int p = blockIdx.x;
    int m = threadIdx.x;                 // 300
    __shared__ __align__(16) float gi[600];
    gi[m]       = g_hbody[p * MDIM + m];
    gi[300 + m] = g_hbody[31 * MDIM + m];  // para_rep == h_body[31]
    __syncthreads();
    float acc = b_sel[m];
    const float4* wr4 = (const float4*)(w_sel + (size_t)m * 600);
    const float4* gi4 = (const float4*)gi;
#pragma unroll 10
    for (int q4 = 0; q4 < 150; q4++) {
        float4 w = wr4[q4], v = gi4[q4];
        acc += w.x * v.x + w.y * v.y + w.z * v.z + w.w * v.w;
    }
    g_gatel[p * MDIM + m] = acc;
}

// softmax over features per row, weighted sum over rows; also emit rhidden ------
__global__ void finalize(float* __restrict__ out)
{
    int tid = threadIdx.x;               // 512
    __shared__ float red[512];
    float acc = 0.f;
    for (int p = 0; p < 32; p++) {
        float v = (tid < 300) ? g_gatel[p * MDIM + tid] : -3.0e38f;
        red[tid] = v; __syncthreads();
        for (int s = 256; s > 0; s >>= 1) {
            if (tid < s) red[tid] = fmaxf(red[tid], red[tid + s]);
            __syncthreads();
        }
        float mx = red[0]; __syncthreads();
        float e = (tid < 300) ? __expf(v - mx) : 0.f;
        red[tid] = e; __syncthreads();
        for (int s = 256; s > 0; s >>= 1) {
            if (tid < s) red[tid] += red[tid + s];
            __syncthreads();
        }
        float sm = red[0]; __syncthreads();
        if (tid < 300) acc += g_hbody[p * MDIM + tid] * __fdividef(e, sm);
    }
    if (tid < 300) {
        out[tid] = acc;                                    // h_body_prime
        out[300 + tid] = g_c[62 * MDIM + tid];             // rhidden = root c of head (b=0)
    }
}

// ---------------- launch ----------------
extern "C" void kernel_launch(void* const* d_in, const int* in_sizes, int n_in,
                              void* d_out, int out_size)
{
    const float* emb     = (const float*)d_in[0];
    const int*   headt   = (const int*)d_in[1];
    const int*   bodyt   = (const int*)d_in[2];
    const float* w_ioux  = (const float*)d_in[3];
    const float* b_ioux  = (const float*)d_in[4];
    const float* w_iouh  = (const float*)d_in[5];
    const float* b_iouh  = (const float*)d_in[6];
    const float* w_fx    = (const float*)d_in[7];
    const float* b_fx    = (const float*)d_in[8];
    const float* w_fh    = (const float*)d_in[9];
    const float* b_fh    = (const float*)d_in[10];
    const float* w_ih_pf = (const float*)d_in[11];
    const float* w_hh_pf = (const float*)d_in[12];
    const float* b_ih_pf = (const float*)d_in[13];
    const float* b_hh_pf = (const float*)d_in[14];
    const float* w_ih_pr = (const float*)d_in[15];
    const float* w_hh_pr = (const float*)d_in[16];
    const float* b_ih_pr = (const float*)d_in[17];
    const float* b_hh_pr = (const float*)d_in[18];
    const float* w_ih_bd = (const float*)d_in[19];
    const float* w_hh_bd = (const float*)d_in[20];
    const float* b_ih_bd = (const float*)d_in[21];
    const float* b_hh_bd = (const float*)d_in[22];
    const float* w_sel   = (const float*)d_in[23];
    const float* b_sel   = (const float*)d_in[24];
    float* out = (float*)d_out;

    float *p_xproj, *p_c, *p_g1, *p_g2, *p_wx, *p_biasx, *p_bbd, *p_xgbd, *p_phid;
    cudaGetSymbolAddress((void**)&p_xproj, g_xproj);
    cudaGetSymbolAddress((void**)&p_c,     g_c);
    cudaGetSymbolAddress((void**)&p_g1,    g_g1);
    cudaGetSymbolAddress((void**)&p_g2,    g_g2);
    cudaGetSymbolAddress((void**)&p_wx,    g_wx);
    cudaGetSymbolAddress((void**)&p_biasx, g_biasx);
    cudaGetSymbolAddress((void**)&p_bbd,   g_bias_bd);
    cudaGetSymbolAddress((void**)&p_xgbd,  g_xg_bd);
    cudaGetSymbolAddress((void**)&p_phid,  g_phidden);

    // 1. prep (biases + x-weight + dedup map init + padded whh)
    prep_kernel<<<(686600 + 255) / 256, 256>>>(b_ioux, b_iouh, b_fx,
                                               b_ih_pf, b_hh_pf, b_ih_pr, b_hh_pr,
                                               b_ih_bd, b_hh_bd, w_ioux, w_fx,
                                               w_hh_pf, w_hh_pr, w_hh_bd);

    // 2-3. dedup claim + assign
    dedup_claim<<<(NROWS + 255) / 256, 256>>>(headt, bodyt);
    dedup_assign<<<(NROWS + 255) / 256, 256>>>(headt, bodyt);

    // 4. x-projection GEMM over UNIQUE tokens (launch #4 -> ncu capture slot)
    gemm300<0><<<dim3(10, (VOCAB + 127) / 128), 256>>>(
        emb, p_wx, p_biasx, p_xproj, VOCAB, NCX, nullptr, nullptr, 0, 0, 0);

    // 5. row -> unique-id gather (only needed by leaf/node)
    dedup_gather<<<(NROWS + 255) / 256, 256>>>(headt, bodyt);

    // 6. tree level 0 (leaves)
    {
        int total = NB * 32 * 75;
        leaf_kernel_f4<<<(total + 255) / 256, 256>>>(total);
    }

    // 7. tree levels 1..5: ONE merged GEMM launch (iou + f) + node combine
    const int sizes[5] = {16, 8, 4, 2, 1};
    const int offs[5]  = {32, 48, 56, 60, 62};
    const int offp[5]  = {0, 32, 48, 56, 60};
    for (int l = 0; l < 5; l++) {
        int sz = sizes[l];
        int rows1 = NB * sz, rows2 = rows1 * 2;
        gemm300<12><<<dim3(11, (rows2 + 127) / 128), 256>>>(
            p_c, w_iouh, nullptr, p_g1, rows1, 0, w_fh, p_g2, sz, offp[l], 0);
        int total = rows1 * 75;
        node_kernel_f4<<<(total + 255) / 256, 256>>>(sz, offs[l], offp[l], b_fh, total);
    }

    // 8. paragraph LSTM x-gates, fwd + rev in ONE launch (MODE 5)
    gemm300<5><<<dim3(5, 16), 256>>>(p_c, w_ih_pf, nullptr, nullptr, 1024, 600,
                                     w_ih_pr, nullptr, 0, 0, 0);

    // 9. paragraph bi-LSTM recurrence: single fused launch (block-local chains)
    para_all<<<dim3(8, 2), 600>>>();

    // 10. body LSTM x-gates + scan
    gemm300<4><<<dim3(5, 1), 256>>>(p_phid, w_ih_bd, p_bbd, p_xgbd, 32, 600,
                                    nullptr, nullptr, 0, 0, 0);
    body_scan<<<1, 600>>>();

    // 11. selective gating + outputs
    gate_logits<<<32, 300>>>(w_sel, b_sel);
    finalize<<<1, 512>>>(out);
}

// round 13
// speedup vs baseline: 1.1990x; 1.1990x over previous
#include <cuda_runtime.h>
#include <cuda_bf16.h>
#include <math.h>

// ---------------- problem constants ----------------
#define NB     1025          // 1 + P*S sentences
#define NNODE  63
#define NROWS  (NB*NNODE)    // 64575
#define VOCAB  50000
#define IN_D   300
#define MDIM   300           // 2*mem_dim
#define MEMD   150
#define G3     900           // 3*M
#define NCX    1200          // 3M + M  (iou + f)
#define PP     32
#define SS     32

// ---------------- device scratch (static; no allocation APIs) ----------------
__device__ float g_xproj[VOCAB * NCX];        // 240 MB : per-UNIQUE-token [iou(900)|f(300)]
__device__ float g_h[NROWS * MDIM];           // tree h
__device__ float g_c[NROWS * MDIM];           // tree c
__device__ float g_g1[NB * 16 * G3];          // level GEMM: (c0+c1)@w_iouh^T
__device__ float g_g2[NB * 32 * MDIM];        // level GEMM: c_child@w_fh^T
__device__ float g_wx[NCX * IN_D];            // [w_ioux ; w_fx] combined
__device__ float g_biasx[NCX];
__device__ float g_bias_pf[600];
__device__ float g_bias_pr[600];
__device__ float g_bias_bd[600];
__device__ float g_xg_pf[1024 * 600];
__device__ float g_xg_pr[1024 * 600];
__device__ float g_ph[2 * 32 * MEMD];         // paragraph LSTM h state (fwd,rev)
__device__ float g_pc[2 * 32 * MEMD];
__device__ float g_phidden[32 * MDIM];        // concat(hT_f, hT_r)
__device__ float g_xg_bd[32 * 600];
__device__ float g_hbody[32 * MDIM];
__device__ float g_gatel[32 * MDIM];

// padded (stride-152, zero-filled) recurrent weights for float4 inner loops
__device__ float g_whh_pf_p[600 * 152];
__device__ float g_whh_pr_p[600 * 152];
__device__ float g_whh_bd_p[600 * 152];

// token dedup
__device__ int g_map[VOCAB];                  // tok -> winning row (claim phase)
__device__ int g_tokid[VOCAB];                // tok -> compact unique id
__device__ int g_utok[VOCAB];                 // unique id -> tok
__device__ int g_uid[NROWS];                  // row -> unique id
__device__ int g_cnt;

// ---------------- fast transcendentals (MUFU-based, ~1e-6 rel accuracy) --------
__device__ __forceinline__ float sigmf(float x)
{
    float xc = fminf(fmaxf(x, -15.f), 15.f);
    return __fdividef(1.f, 1.f + __expf(-xc));
}
__device__ __forceinline__ float tanhfast(float x)
{
    float xc = fminf(fmaxf(x, -15.f), 15.f);
    float e = __expf(2.f * xc);
    return __fdividef(e - 1.f, e + 1.f);
}

__device__ __forceinline__ int row_tok(int r, const int* __restrict__ headt,
                                       const int* __restrict__ bodyt)
{
    return (r < NNODE) ? headt[r] : bodyt[r - NNODE];
}

// ---------------- split-TF32 helpers ----------------
__device__ __forceinline__ void tf32_split(float v, float& hf, float& lf)
{
    unsigned h; asm("cvt.rna.tf32.f32 %0, %1;" : "=r"(h) : "f"(v));
    hf = __uint_as_float(h);
    float lo = v - hf;
    unsigned l; asm("cvt.rna.tf32.f32 %0, %1;" : "=r"(l) : "f"(lo));
    lf = __uint_as_float(l);
}

__device__ __forceinline__ void mma_tf32(float* d, const unsigned* a, const unsigned* b)
{
    asm volatile("mma.sync.aligned.m16n8k8.row.col.f32.tf32.tf32.f32 "
                 "{%0,%1,%2,%3}, {%4,%5,%6,%7}, {%8,%9}, {%0,%1,%2,%3};"
                 : "+f"(d[0]), "+f"(d[1]), "+f"(d[2]), "+f"(d[3])
                 : "r"(a[0]), "r"(a[1]), "r"(a[2]), "r"(a[3]),
                   "r"(b[0]), "r"(b[1]));
}

// ---------------- dedup pipeline ----------------
__global__ void dedup_claim(const int* __restrict__ headt, const int* __restrict__ bodyt)
{
    int r = blockIdx.x * 256 + threadIdx.x;
    if (r >= NROWS) return;
    atomicCAS(&g_map[row_tok(r, headt, bodyt)], -1, r);
}
__global__ void dedup_assign(const int* __restrict__ headt, const int* __restrict__ bodyt)
{
    int r = blockIdx.x * 256 + threadIdx.x;
    if (r >= NROWS) return;
    int tok = row_tok(r, headt, bodyt);
    if (g_map[tok] == r) {                    // winner allocates the compact id
        int id = atomicAdd(&g_cnt, 1);
        g_tokid[tok] = id;
        g_utok[id] = tok;
    }
}
__global__ void dedup_gather(const int* __restrict__ headt, const int* __restrict__ bodyt)
{
    int r = blockIdx.x * 256 + threadIdx.x;
    if (r >= NROWS) return;
    g_uid[r] = g_tokid[row_tok(r, headt, bodyt)];
}

// ---------------- prep: biases, combined x-weight, map init, padded whh -------
__global__ void prep_kernel(const float* __restrict__ b_ioux, const float* __restrict__ b_iouh,
                            const float* __restrict__ b_fx,
                            const float* __restrict__ b_ih_pf, const float* __restrict__ b_hh_pf,
                            const float* __restrict__ b_ih_pr, const float* __restrict__ b_hh_pr,
                            const float* __restrict__ b_ih_bd, const float* __restrict__ b_hh_bd,
                            const float* __restrict__ w_ioux, const float* __restrict__ w_fx,
                            const float* __restrict__ w_hh_pf, const float* __restrict__ w_hh_pr,
                            const float* __restrict__ w_hh_bd)
{
    int i = blockIdx.x * 256 + threadIdx.x;
    if (i < 900)            g_biasx[i] = b_ioux[i] + b_iouh[i];
    else if (i < 1200)      g_biasx[i] = b_fx[i - 900];
    else if (i < 1800)      { int q = i - 1200; g_bias_pf[q] = b_ih_pf[q] + b_hh_pf[q]; }
    else if (i < 2400)      { int q = i - 1800; g_bias_pr[q] = b_ih_pr[q] + b_hh_pr[q]; }
    else if (i < 3000)      { int q = i - 2400; g_bias_bd[q] = b_ih_bd[q] + b_hh_bd[q]; }
    else if (i < 273000)    { int q = i - 3000;   g_wx[q] = w_ioux[q]; }
    else if (i < 363000)    { int q = i - 273000; g_wx[270000 + q] = w_fx[q]; }
    else if (i < 413000)    { int q = i - 363000; g_map[q] = -1; if (q == 0) g_cnt = 0; }
    else if (i < 504200)    { int q = i - 413000; int r = q / 152, k = q - r * 152;
                              g_whh_pf_p[q] = (k < 150) ? w_hh_pf[r * 150 + k] : 0.f; }
    else if (i < 595400)    { int q = i - 504200; int r = q / 152, k = q - r * 152;
                              g_whh_pr_p[q] = (k < 150) ? w_hh_pr[r * 150 + k] : 0.f; }
    else if (i < 686600)    { int q = i - 595400; int r = q / 152, k = q - r * 152;
                              g_whh_bd_p[q] = (k < 150) ? w_hh_bd[r * 150 + k] : 0.f; }
}

// ---------------- generic K=300 GEMM:  C[r,n] = sum_k A(r,k) * W[n,k] + bias[n] ----
// MODE 0 : A(r,k) = emb[g_utok[r]*300+k], rows = g_cnt (dynamic, early-exit)
// MODE 4 : A(r,k) = A[r*300+k]          (plain)
// MODE 5 : MERGED para x-gate launch: blockIdx.y>=8 -> reverse job.
//          A(r,k) = c_root of sentence (row r = t*32+p, time-reversed for job 1);
//          W/bias/C selected per job.
// MODE 12: MERGED tree-level launch. blockIdx.x<8 -> iou GEMM
//          (A = c[child0]+c[child1], W, C, ncols=900, rows);
//          blockIdx.x>=8 -> f GEMM (A = c[child], W2, C2, ncols=300, rows*2).
//
// TENSOR-CORE core (R10 proven layout): 128x128 CTA tile, 8 warps in 2x4,
// split-TF32 mma.sync m16n8k8 (3 MMAs: hi*hi + hi*lo + lo*hi == fp32 accuracy).
// A/B split into tf32 hi/lo PLANES at smem-fill time, stored [row][k] with
// stride 20 so every fragment LDS.32 is 32-bank conflict-free. K-tile 16,
// single-buffered smem with register prefetch of the next tile.
template<int MODE>
__global__ void __launch_bounds__(256, 2) gemm300(
    const float* __restrict__ A, const float* __restrict__ W,
    const float* __restrict__ bias, float* __restrict__ C,
    int rows, int ncols,
    const float* __restrict__ W2, float* __restrict__ C2,
    int size, int offPrev, int rev)
{
    __shared__ __align__(16) float Ah[128 * 20], Al[128 * 20];
    __shared__ __align__(16) float Bh[128 * 20], Bl[128 * 20];
    __shared__ int rbase[128];

    const int tid = threadIdx.x;

    bool m2 = false;
    int job = 0;
    int rowBase, colBase;
    const float* Wsel = W;
    float*       Csel = C;
    const float* biasE = bias;
    int ncolsE = ncols;
    int nrows;
    if (MODE == 12) {
        rowBase = blockIdx.y * 128;
        m2 = blockIdx.x >= 8;
        colBase = m2 ? (blockIdx.x - 8) * 128 : blockIdx.x * 128;
        Wsel = m2 ? W2 : W;
        Csel = m2 ? C2 : C;
        ncolsE = m2 ? MDIM : G3;
        nrows = m2 ? rows * 2 : rows;
    } else if (MODE == 5) {
        job = blockIdx.y >> 3;
        rowBase = (blockIdx.y & 7) * 128;
        colBase = blockIdx.x * 128;
        Wsel = job ? W2 : W;
        Csel = job ? g_xg_pr : g_xg_pf;
        biasE = job ? g_bias_pr : g_bias_pf;
        ncolsE = 600;
        nrows = 1024;
    } else {
        rowBase = blockIdx.y * 128;
        colBase = blockIdx.x * 128;
        nrows = (MODE == 0) ? g_cnt : rows;
    }
    if ((MODE == 0 || MODE == 12) && rowBase >= nrows) return;   // uniform per block

    if (tid < 128) {
        int r = rowBase + tid;
        int rb = -1;
        if (r < nrows) {
            if (MODE == 0)       { rb = g_utok[r] * 300; }
            else if (MODE == 12) {
                if (!m2) { int b = r / size; int kk = r - b * size;
                           rb = (b * NNODE + offPrev + 2 * kk) * MDIM; }
                else     { int s2 = size * 2; int b = r / s2; int rem = r - b * s2;
                           rb = (b * NNODE + offPrev + rem) * MDIM; }
            }
            else if (MODE == 5)  { int t = r >> 5, p = r & 31; int te = job ? 31 - t : t;
                                   rb = ((1 + p * 32 + te) * NNODE + 62) * MDIM; }
            else                 rb = r * 300;
        }
        rbase[tid] = rb;
    }
    __syncthreads();

    // loader mapping: 256 threads; each loads 2 A-rows and 2 W-rows, one float4 each
    const int lrow = tid >> 2;            // 0..63
    const int kq   = (tid & 3) * 4;       // k offset within 16-wide tile: 0,4,8,12
    const int arb0 = rbase[lrow];
    const int arb1 = rbase[lrow + 64];
    const int wr0  = colBase + lrow;
    const int wr1  = colBase + lrow + 64;
    const bool w0ok = wr0 < ncolsE;
    const bool w1ok = wr1 < ncolsE;
    const float* wp0 = Wsel + (size_t)(w0ok ? wr0 : 0) * 300;
    const float* wp1 = Wsel + (size_t)(w1ok ? wr1 : 0) * 300;

    // mma fragment mapping
    const int w    = tid >> 5, lane = tid & 31;
    const int g    = lane >> 2, t4 = lane & 3;
    const int wrr  = w & 1;               // 0..1 -> 64-row group
    const int wcc  = w >> 1;              // 0..3 -> 32-col group

    float c[4][4][4];                     // [mtile][ntile][reg], 64 accum regs
#pragma unroll
    for (int mt = 0; mt < 4; mt++)
#pragma unroll
        for (int nt = 0; nt < 4; nt++)
#pragma unroll
            for (int q = 0; q < 4; q++) c[mt][nt][q] = 0.f;

    float4 a0v, a1v, w0v, w1v;

    auto LOADT = [&](int k0) {
        const float4 Z = make_float4(0.f, 0.f, 0.f, 0.f);
        a0v = Z; a1v = Z; w0v = Z; w1v = Z;
        int k = k0 + kq;
        if (k < 300) {
            if (arb0 >= 0) {
                a0v = *(const float4*)(A + arb0 + k);
                if (MODE == 12 && !m2) {
                    float4 t2 = *(const float4*)(A + arb0 + 300 + k);
                    a0v.x += t2.x; a0v.y += t2.y; a0v.z += t2.z; a0v.w += t2.w;
                }
            }
            if (arb1 >= 0) {
                a1v = *(const float4*)(A + arb1 + k);
                if (MODE == 12 && !m2) {
                    float4 t2 = *(const float4*)(A + arb1 + 300 + k);
                    a1v.x += t2.x; a1v.y += t2.y; a1v.z += t2.z; a1v.w += t2.w;
                }
            }
            if (w0ok) w0v = *(const float4*)(wp0 + k);
            if (w1ok) w1v = *(const float4*)(wp1 + k);
        }
    };

    auto SPLIT4 = [&](float4 v, float* hp, float* lp) {
        float4 h, l;
        tf32_split(v.x, h.x, l.x); tf32_split(v.y, h.y, l.y);
        tf32_split(v.z, h.z, l.z); tf32_split(v.w, h.w, l.w);
        *(float4*)hp = h; *(float4*)lp = l;
    };

    auto STORET = [&]() {
        int s0 = lrow * 20 + kq;
        int s1 = (lrow + 64) * 20 + kq;
        SPLIT4(a0v, &Ah[s0], &Al[s0]);
        SPLIT4(a1v, &Ah[s1], &Al[s1]);
        SPLIT4(w0v, &Bh[s0], &Bl[s0]);
        SPLIT4(w1v, &Bh[s1], &Bl[s1]);
    };

    LOADT(0);
    for (int k0 = 0; k0 < 300; k0 += 16) {
        STORET();
        __syncthreads();
        if (k0 + 16 < 300) LOADT(k0 + 16);    // prefetch hidden under the MMAs
#pragma unroll
        for (int ks = 0; ks < 2; ks++) {
            const int kb = ks * 8;
            unsigned bh[4][2], bl[4][2];
#pragma unroll
            for (int nt = 0; nt < 4; nt++) {
                int cb = (wcc * 32 + nt * 8 + g) * 20 + kb + t4;
                bh[nt][0] = __float_as_uint(Bh[cb]);
                bh[nt][1] = __float_as_uint(Bh[cb + 4]);
                bl[nt][0] = __float_as_uint(Bl[cb]);
                bl[nt][1] = __float_as_uint(Bl[cb + 4]);
            }
#pragma unroll
            for (int mt = 0; mt < 4; mt++) {
                int rb0 = (wrr * 64 + mt * 16 + g) * 20 + kb + t4;
                int rb1 = rb0 + 8 * 20;
                unsigned ah[4] = { __float_as_uint(Ah[rb0]), __float_as_uint(Ah[rb1]),
                                   __float_as_uint(Ah[rb0 + 4]), __float_as_uint(Ah[rb1 + 4]) };
                unsigned al[4] = { __float_as_uint(Al[rb0]), __float_as_uint(Al[rb1]),
                                   __float_as_uint(Al[rb0 + 4]), __float_as_uint(Al[rb1 + 4]) };
#pragma unroll
                for (int nt = 0; nt < 4; nt++) {
                    mma_tf32(c[mt][nt], ah, bh[nt]);   // hi*hi
                    mma_tf32(c[mt][nt], ah, bl[nt]);   // hi*lo
                    mma_tf32(c[mt][nt], al, bh[nt]);   // lo*hi
                }
            }
        }
        __syncthreads();
    }

    // epilogue: c regs -> D rows (g, g+8), cols (2t, 2t+1). ncolsE is even, col
    // even -> float2 store in-bounds iff col < ncolsE. 8B-aligned.
#pragma unroll
    for (int mt = 0; mt < 4; mt++) {
        int r0 = rowBase + wrr * 64 + mt * 16 + g;
        int r1 = r0 + 8;
#pragma unroll
        for (int nt = 0; nt < 4; nt++) {
            int col = colBase + wcc * 32 + nt * 8 + 2 * t4;
            if (col >= ncolsE) continue;
            float bx = 0.f, by = 0.f;
            if (biasE) { float2 bv = *(const float2*)(biasE + col); bx = bv.x; by = bv.y; }
            if (r0 < nrows) {
                float2 v = make_float2(c[mt][nt][0] + bx, c[mt][nt][1] + by);
                *(float2*)(Csel + (size_t)r0 * ncolsE + col) = v;
            }
            if (r1 < nrows) {
                float2 v = make_float2(c[mt][nt][2] + bx, c[mt][nt][3] + by);
                *(float2*)(Csel + (size_t)r1 * ncolsE + col) = v;
            }
        }
    }
}

// ---------------- tree level 0 (leaves), float4-vectorized -----------------
__global__ void __launch_bounds__(256) leaf_kernel_f4(int total)   // total = NB*32*75
{
    int e = blockIdx.x * 256 + threadIdx.x;
    if (e >= total) return;
    int n = e / 75, q = e - n * 75;       // node index, float4 chunk
    int b = n >> 5, leaf = n & 31;
    int pos = b * NNODE + leaf;
    const float4* xr = (const float4*)(g_xproj + (size_t)g_uid[pos] * NCX);
    float4 iv = xr[q], ov = xr[75 + q], uv = xr[150 + q];
    float4 cv, hv;
    { float i = sigmf(iv.x), o = sigmf(ov.x), u = tanhfast(uv.x);
      cv.x = i * u; hv.x = o * tanhfast(cv.x); }
    { float i = sigmf(iv.y), o = sigmf(ov.y), u = tanhfast(uv.y);
      cv.y = i * u; hv.y = o * tanhfast(cv.y); }
    { float i = sigmf(iv.z), o = sigmf(ov.z), u = tanhfast(uv.z);
      cv.z = i * u; hv.z = o * tanhfast(cv.z); }
    { float i = sigmf(iv.w), o = sigmf(ov.w), u = tanhfast(uv.w);
      cv.w = i * u; hv.w = o * tanhfast(cv.w); }
    ((float4*)g_c)[(size_t)pos * 75 + q] = cv;
    ((float4*)g_h)[(size_t)pos * 75 + q] = hv;
}

// ---------------- tree levels 1..5, float4-vectorized ----------------------
__global__ void __launch_bounds__(256) node_kernel_f4(
    int size, int off, int offPrev, const float* __restrict__ b_fh, int total)
{
    int e = blockIdx.x * 256 + threadIdx.x;
    if (e >= total) return;               // total = NB*size*75
    int n = e / 75, q = e - n * 75;       // n = b*size+kk == grow
    int b = n / size, kk = n - b * size;
    int node = off + kk;
    int pos = b * NNODE + node;
    const float4* xr  = (const float4*)(g_xproj + (size_t)g_uid[pos] * NCX);
    const float4* g1r = (const float4*)(g_g1 + (size_t)n * G3);
    const float4* g2r = (const float4*)(g_g2 + (size_t)n * (2 * MDIM));
    int ch = offPrev + 2 * kk;
    const float4* h0 = (const float4*)g_h + (size_t)(b * NNODE + ch) * 75;

    float4 iv = xr[q],       ovv = xr[75 + q],  uvv = xr[150 + q], fxv = xr[225 + q];
    float4 g1a = g1r[q],     g1b = g1r[75 + q], g1c = g1r[150 + q];
    float4 g2a = g2r[q],     g2b = g2r[75 + q];
    float4 bf  = ((const float4*)b_fh)[q];
    float4 h0v = h0[q],      h1v = h0[75 + q];

    float4 cv, hv;
    { float i = sigmf(iv.x + g1a.x), o = sigmf(ovv.x + g1b.x), u = tanhfast(uvv.x + g1c.x);
      float fx = fxv.x + bf.x;
      float f0 = sigmf(g2a.x + fx), f1 = sigmf(g2b.x + fx);
      cv.x = i * u + f0 * h0v.x + f1 * h1v.x; hv.x = o * tanhfast(cv.x); }
    { float i = sigmf(iv.y + g1a.y), o = sigmf(ovv.y + g1b.y), u = tanhfast(uvv.y + g1c.y);
      float fx = fxv.y + bf.y;
      float f0 = sigmf(g2a.y + fx), f1 = sigmf(g2b.y + fx);
      cv.y = i * u + f0 * h0v.y + f1 * h1v.y; hv.y = o * tanhfast(cv.y); }
    { float i = sigmf(iv.z + g1a.z), o = sigmf(ovv.z + g1b.z), u = tanhfast(uvv.z + g1c.z);
      float fx = fxv.z + bf.z;
      float f0 = sigmf(g2a.z + fx), f1 = sigmf(g2b.z + fx);
      cv.z = i * u + f0 * h0v.z + f1 * h1v.z; hv.z = o * tanhfast(cv.z); }
    { float i = sigmf(iv.w + g1a.w), o = sigmf(ovv.w + g1b.w), u = tanhfast(uvv.w + g1c.w);
      float fx = fxv.w + bf.w;
      float f0 = sigmf(g2a.w + fx), f1 = sigmf(g2b.w + fx);
      cv.w = i * u + f0 * h0v.w + f1 * h1v.w; hv.w = o * tanhfast(cv.w); }
    ((float4*)g_c)[(size_t)pos * 75 + q] = cv;
    ((float4*)g_h)[(size_t)pos * 75 + q] = hv;
}

// ---------------- paragraph bi-LSTM: ALL 32 steps in one launch ----------------
__global__ void para_all()
{
    int job = blockIdx.y;                // 0 = fwd, 1 = rev
    int pb = blockIdx.x * 4;
    const float* xg  = job ? g_xg_pr : g_xg_pf;
    const float* whp = job ? g_whh_pr_p : g_whh_pf_p;
    float* hs = g_ph + job * 32 * MEMD;
    float* cs = g_pc + job * 32 * MEMD;
    __shared__ __align__(16) float hsh[608];   // 4 regions x 152 (pads zeroed)
    __shared__ float gsh[2400];                // 4 x 600
    int j = threadIdx.x;                       // 600
    if (j < 8) { int r = j >> 1; hsh[r * 152 + 150 + (j & 1)] = 0.f; }
    const float4* wr4 = (const float4*)(whp + (size_t)j * 152);
    for (int t = 0; t < 32; t++) {
        if (t > 0) { int pp = j / MEMD, m = j % MEMD;
                     hsh[pp * 152 + m] = hs[(pb + pp) * MEMD + m]; }
        __syncthreads();

        int xb = ((t << 5) + pb) * 600 + j;
        float a0 = xg[xb], a1 = xg[xb + 600], a2 = xg[xb + 1200], a3 = xg[xb + 1800];
        if (t > 0) {
#pragma unroll 19
            for (int k4 = 0; k4 < 38; k4++) {
                float4 w  = wr4[k4];
                float4 h0 = *(const float4*)&hsh[k4 * 4];
                float4 h1 = *(const float4*)&hsh[152 + k4 * 4];
                float4 h2 = *(const float4*)&hsh[304 + k4 * 4];
                float4 h3 = *(const float4*)&hsh[456 + k4 * 4];
                a0 += w.x * h0.x + w.y * h0.y + w.z * h0.z + w.w * h0.w;
                a1 += w.x * h1.x + w.y * h1.y + w.z * h1.z + w.w * h1.w;
                a2 += w.x * h2.x + w.y * h2.y + w.z * h2.z + w.w * h2.w;
                a3 += w.x * h3.x + w.y * h3.y + w.z * h3.z + w.w * h3.w;
            }
        }
        gsh[j] = a0; gsh[600 + j] = a1; gsh[1200 + j] = a2; gsh[1800 + j] = a3;
        __syncthreads();

        int pp = j / MEMD, m = j % MEMD;
        int p = pb + pp;
        const float* gp = gsh + pp * 600;
        float gi = gp[m], gf = gp[150 + m], gg = gp[300 + m], go = gp[450 + m];
        float cprev = (t > 0) ? cs[p * MEMD + m] : 0.f;
        float c2 = sigmf(gf) * cprev + sigmf(gi) * tanhfast(gg);
        float h2 = sigmf(go) * tanhfast(c2);
        cs[p * MEMD + m] = c2;
        hs[p * MEMD + m] = h2;
        if (t == 31) g_phidden[p * MDIM + job * MEMD + m] = h2;
        __syncthreads();                 // h/c writes visible before next t's hsh load
    }
}

// ---------------- body LSTM scan (upstream quirk: bwd cell uses fresh fwd h) ---
__global__ void body_scan()
{
    __shared__ __align__(16) float hf[152];
    __shared__ float cf[MEMD], cb[MEMD], g[600];
    int j = threadIdx.x;                 // 600
    if (j < 2) hf[150 + j] = 0.f;        // pad
    const float4* wr4 = (const float4*)(g_whh_bd_p + (size_t)j * 152);
    __syncthreads();
    for (int t = 0; t < 32; t++) {
        float acc = g_xg_bd[t * 600 + j];
        if (t > 0) {
#pragma unroll 19
            for (int k4 = 0; k4 < 38; k4++) {
                float4 w = wr4[k4];
                float4 h = *(const float4*)&hf[k4 * 4];
                acc += w.x * h.x + w.y * h.y + w.z * h.z + w.w * h.w;
            }
        }
        g[j] = acc;
        __syncthreads();
        if (j < MEMD) {
            float cprev = (t > 0) ? cf[j] : 0.f;
            float c2 = sigmf(g[150 + j]) * cprev + sigmf(g[j]) * tanhfast(g[300 + j]);
            float h2 = sigmf(g[450 + j]) * tanhfast(c2);
            cf[j] = c2; hf[j] = h2;
            g_hbody[t * MDIM + j] = h2;
        }
        __syncthreads();
        float acc2 = g_xg_bd[(31 - t) * 600 + j];
        {
#pragma unroll 19
            for (int k4 = 0; k4 < 38; k4++) {
                float4 w = wr4[k4];
                float4 h = *(const float4*)&hf[k4 * 4];   // hf == fresh h_f2
                acc2 += w.x * h.x + w.y * h.y + w.z * h.z + w.w * h.w;
            }
        }
        g[j] = acc2;
        __syncthreads();
        if (j < MEMD) {
            float cprev = (t > 0) ? cb[j] : 0.f;
            float c2 = sigmf(g[150 + j]) * cprev + sigmf(g[j]) * tanhfast(g[300 + j]);
            float h2 = sigmf(g[450 + j]) * tanhfast(c2);
            cb[j] = c2;
            g_hbody[t * MDIM + 150 + j] = h2;
        }
        __syncthreads();
    }
}

// ---------------- gating: logits[p,m] = w_sel[m,:] . [h_body[p] ; para_rep] ----
__global__ void gate_logits(const float* __restrict__ w_sel, const float* __restrict__ b_sel)
{
    int p = blockIdx.x;
    int m = threadIdx.x;                 // 300
    __shared__ __align__(16) float gi[600];
    gi[m]       = g_hbody[p * MDIM + m];
    gi[300 + m] = g_hbody[31 * MDIM + m];  // para_rep == h_body[31]
    __syncthreads();
    float acc = b_sel[m];
    const float4* wr4 = (const float4*)(w_sel + (size_t)m * 600);
    const float4* gi4 = (const float4*)gi;
#pragma unroll 10
    for (int q4 = 0; q4 < 150; q4++) {
        float4 w = wr4[q4], v = gi4[q4];
        acc += w.x * v.x + w.y * v.y + w.z * v.z + w.w * v.w;
    }
    g_gatel[p * MDIM + m] = acc;
}

// softmax over features per row, weighted sum over rows; also emit rhidden ------
__global__ void finalize(float* __restrict__ out)
{
    int tid = threadIdx.x;               // 512
    __shared__ float red[512];
    float acc = 0.f;
    for (int p = 0; p < 32; p++) {
        float v = (tid < 300) ? g_gatel[p * MDIM + tid] : -3.0e38f;
        red[tid] = v; __syncthreads();
        for (int s = 256; s > 0; s >>= 1) {
            if (tid < s) red[tid] = fmaxf(red[tid], red[tid + s]);
            __syncthreads();
        }
        float mx = red[0]; __syncthreads();
        float e = (tid < 300) ? __expf(v - mx) : 0.f;
        red[tid] = e; __syncthreads();
        for (int s = 256; s > 0; s >>= 1) {
            if (tid < s) red[tid] += red[tid + s];
            __syncthreads();
        }
        float sm = red[0]; __syncthreads();
        if (tid < 300) acc += g_hbody[p * MDIM + tid] * __fdividef(e, sm);
    }
    if (tid < 300) {
        out[tid] = acc;                                    // h_body_prime
        out[300 + tid] = g_c[62 * MDIM + tid];             // rhidden = root c of head (b=0)
    }
}

// ---------------- launch ----------------
extern "C" void kernel_launch(void* const* d_in, const int* in_sizes, int n_in,
                              void* d_out, int out_size)
{
    const float* emb     = (const float*)d_in[0];
    const int*   headt   = (const int*)d_in[1];
    const int*   bodyt   = (const int*)d_in[2];
    const float* w_ioux  = (const float*)d_in[3];
    const float* b_ioux  = (const float*)d_in[4];
    const float* w_iouh  = (const float*)d_in[5];
    const float* b_iouh  = (const float*)d_in[6];
    const float* w_fx    = (const float*)d_in[7];
    const float* b_fx    = (const float*)d_in[8];
    const float* w_fh    = (const float*)d_in[9];
    const float* b_fh    = (const float*)d_in[10];
    const float* w_ih_pf = (const float*)d_in[11];
    const float* w_hh_pf = (const float*)d_in[12];
    const float* b_ih_pf = (const float*)d_in[13];
    const float* b_hh_pf = (const float*)d_in[14];
    const float* w_ih_pr = (const float*)d_in[15];
    const float* w_hh_pr = (const float*)d_in[16];
    const float* b_ih_pr = (const float*)d_in[17];
    const float* b_hh_pr = (const float*)d_in[18];
    const float* w_ih_bd = (const float*)d_in[19];
    const float* w_hh_bd = (const float*)d_in[20];
    const float* b_ih_bd = (const float*)d_in[21];
    const float* b_hh_bd = (const float*)d_in[22];
    const float* w_sel   = (const float*)d_in[23];
    const float* b_sel   = (const float*)d_in[24];
    float* out = (float*)d_out;

    float *p_xproj, *p_c, *p_g1, *p_g2, *p_wx, *p_biasx, *p_bbd, *p_xgbd, *p_phid;
    cudaGetSymbolAddress((void**)&p_xproj, g_xproj);
    cudaGetSymbolAddress((void**)&p_c,     g_c);
    cudaGetSymbolAddress((void**)&p_g1,    g_g1);
    cudaGetSymbolAddress((void**)&p_g2,    g_g2);
    cudaGetSymbolAddress((void**)&p_wx,    g_wx);
    cudaGetSymbolAddress((void**)&p_biasx, g_biasx);
    cudaGetSymbolAddress((void**)&p_bbd,   g_bias_bd);
    cudaGetSymbolAddress((void**)&p_xgbd,  g_xg_bd);
    cudaGetSymbolAddress((void**)&p_phid,  g_phidden);

    // 1. prep (biases + x-weight + dedup map init + padded whh)
    prep_kernel<<<(686600 + 255) / 256, 256>>>(b_ioux, b_iouh, b_fx,
                                               b_ih_pf, b_hh_pf, b_ih_pr, b_hh_pr,
                                               b_ih_bd, b_hh_bd, w_ioux, w_fx,
                                               w_hh_pf, w_hh_pr, w_hh_bd);

    // 2-3. dedup claim + assign
    dedup_claim<<<(NROWS + 255) / 256, 256>>>(headt, bodyt);
    dedup_assign<<<(NROWS + 255) / 256, 256>>>(headt, bodyt);

    // 4. x-projection GEMM over UNIQUE tokens (launch #4 -> ncu capture slot)
    gemm300<0><<<dim3(10, (VOCAB + 127) / 128), 256>>>(
        emb, p_wx, p_biasx, p_xproj, VOCAB, NCX, nullptr, nullptr, 0, 0, 0);

    // 5. row -> unique-id gather (only needed by leaf/node)
    dedup_gather<<<(NROWS + 255) / 256, 256>>>(headt, bodyt);

    // 6. tree level 0 (leaves)
    {
        int total = NB * 32 * 75;
        leaf_kernel_f4<<<(total + 255) / 256, 256>>>(total);
    }

    // 7. tree levels 1..5: ONE merged GEMM launch (iou + f) + node combine
    const int sizes[5] = {16, 8, 4, 2, 1};
    const int offs[5]  = {32, 48, 56, 60, 62};
    const int offp[5]  = {0, 32, 48, 56, 60};
    for (int l = 0; l < 5; l++) {
        int sz = sizes[l];
        int rows1 = NB * sz, rows2 = rows1 * 2;
        gemm300<12><<<dim3(11, (rows2 + 127) / 128), 256>>>(
            p_c, w_iouh, nullptr, p_g1, rows1, 0, w_fh, p_g2, sz, offp[l], 0);
        int total = rows1 * 75;
        node_kernel_f4<<<(total + 255) / 256, 256>>>(sz, offs[l], offp[l], b_fh, total);
    }

    // 8. paragraph LSTM x-gates, fwd + rev in ONE launch (MODE 5)
    gemm300<5><<<dim3(5, 16), 256>>>(p_c, w_ih_pf, nullptr, nullptr, 1024, 600,
                                     w_ih_pr, nullptr, 0, 0, 0);

    // 9. paragraph bi-LSTM recurrence: single fused launch (block-local chains)
    para_all<<<dim3(8, 2), 600>>>();

    // 10. body LSTM x-gates + scan
    gemm300<4><<<dim3(5, 1), 256>>>(p_phid, w_ih_bd, p_bbd, p_xgbd, 32, 600,
                                    nullptr, nullptr, 0, 0, 0);
    body_scan<<<1, 600>>>();

    // 11. selective gating + outputs
    gate_logits<<<32, 300>>>(w_sel, b_sel);
    finalize<<<1, 512>>>(out);
}

// round 14
// speedup vs baseline: 1.2359x; 1.0308x over previous
#include <cuda_runtime.h>
#include <cuda_bf16.h>
#include <math.h>

// ---------------- problem constants ----------------
#define NB     1025          // 1 + P*S sentences
#define NNODE  63
#define NROWS  (NB*NNODE)    // 64575
#define VOCAB  50000
#define IN_D   300
#define MDIM   300           // 2*mem_dim
#define MEMD   150
#define G3     900           // 3*M
#define NCX    1200          // 3M + M  (iou + f)
#define PP     32
#define SS     32

// dynamic smem layout for the GEMM: [buf][plane][2560] floats
#define GP     2560          // floats per plane (128 rows * 20 stride)
#define GBUF   (4 * GP)      // floats per buffer (Ah,Al,Bh,Bl)
#define GEMM_DYN_BYTES (2 * GBUF * 4)   // 81920

// ---------------- device scratch (static; no allocation APIs) ----------------
__device__ float g_xproj[VOCAB * NCX];        // 240 MB : per-UNIQUE-token [iou(900)|f(300)]
__device__ float g_h[NROWS * MDIM];           // tree h
__device__ float g_c[NROWS * MDIM];           // tree c
__device__ float g_g1[NB * 16 * G3];          // level GEMM: (c0+c1)@w_iouh^T
__device__ float g_g2[NB * 32 * MDIM];        // level GEMM: c_child@w_fh^T
__device__ float g_wx[NCX * IN_D];            // [w_ioux ; w_fx] combined
__device__ float g_biasx[NCX];
__device__ float g_bias_pf[600];
__device__ float g_bias_pr[600];
__device__ float g_bias_bd[600];
__device__ float g_xg_pf[1024 * 600];
__device__ float g_xg_pr[1024 * 600];
__device__ float g_ph[2 * 32 * MEMD];         // paragraph LSTM h state (fwd,rev)
__device__ float g_pc[2 * 32 * MEMD];
__device__ float g_phidden[32 * MDIM];        // concat(hT_f, hT_r)
__device__ float g_xg_bd[32 * 600];
__device__ float g_hbody[32 * MDIM];
__device__ float g_gatel[32 * MDIM];

// padded (stride-152, zero-filled) recurrent weights for float4 inner loops
__device__ float g_whh_pf_p[600 * 152];
__device__ float g_whh_pr_p[600 * 152];
__device__ float g_whh_bd_p[600 * 152];

// token dedup
__device__ int g_map[VOCAB];                  // tok -> winning row (claim phase)
__device__ int g_tokid[VOCAB];                // tok -> compact unique id
__device__ int g_utok[VOCAB];                 // unique id -> tok
__device__ int g_uid[NROWS];                  // row -> unique id
__device__ int g_cnt;

// ---------------- fast transcendentals (MUFU-based, ~1e-6 rel accuracy) --------
__device__ __forceinline__ float sigmf(float x)
{
    float xc = fminf(fmaxf(x, -15.f), 15.f);
    return __fdividef(1.f, 1.f + __expf(-xc));
}
__device__ __forceinline__ float tanhfast(float x)
{
    float xc = fminf(fmaxf(x, -15.f), 15.f);
    float e = __expf(2.f * xc);
    return __fdividef(e - 1.f, e + 1.f);
}

__device__ __forceinline__ int row_tok(int r, const int* __restrict__ headt,
                                       const int* __restrict__ bodyt)
{
    return (r < NNODE) ? headt[r] : bodyt[r - NNODE];
}

// ---------------- split-TF32 helpers ----------------
__device__ __forceinline__ void tf32_split(float v, float& hf, float& lf)
{
    unsigned h; asm("cvt.rna.tf32.f32 %0, %1;" : "=r"(h) : "f"(v));
    hf = __uint_as_float(h);
    float lo = v - hf;
    unsigned l; asm("cvt.rna.tf32.f32 %0, %1;" : "=r"(l) : "f"(lo));
    lf = __uint_as_float(l);
}

__device__ __forceinline__ void mma_tf32(float* d, const unsigned* a, const unsigned* b)
{
    asm volatile("mma.sync.aligned.m16n8k8.row.col.f32.tf32.tf32.f32 "
                 "{%0,%1,%2,%3}, {%4,%5,%6,%7}, {%8,%9}, {%0,%1,%2,%3};"
                 : "+f"(d[0]), "+f"(d[1]), "+f"(d[2]), "+f"(d[3])
                 : "r"(a[0]), "r"(a[1]), "r"(a[2]), "r"(a[3]),
                   "r"(b[0]), "r"(b[1]));
}

// ---------------- dedup pipeline ----------------
__global__ void dedup_claim(const int* __restrict__ headt, const int* __restrict__ bodyt)
{
    int r = blockIdx.x * 256 + threadIdx.x;
    if (r >= NROWS) return;
    atomicCAS(&g_map[row_tok(r, headt, bodyt)], -1, r);
}
__global__ void dedup_assign(const int* __restrict__ headt, const int* __restrict__ bodyt)
{
    int r = blockIdx.x * 256 + threadIdx.x;
    if (r >= NROWS) return;
    int tok = row_tok(r, headt, bodyt);
    if (g_map[tok] == r) {                    // winner allocates the compact id
        int id = atomicAdd(&g_cnt, 1);
        g_tokid[tok] = id;
        g_utok[id] = tok;
    }
}
__global__ void dedup_gather(const int* __restrict__ headt, const int* __restrict__ bodyt)
{
    int r = blockIdx.x * 256 + threadIdx.x;
    if (r >= NROWS) return;
    g_uid[r] = g_tokid[row_tok(r, headt, bodyt)];
}

// ---------------- prep: biases, combined x-weight, map init, padded whh -------
__global__ void prep_kernel(const float* __restrict__ b_ioux, const float* __restrict__ b_iouh,
                            const float* __restrict__ b_fx,
                            const float* __restrict__ b_ih_pf, const float* __restrict__ b_hh_pf,
                            const float* __restrict__ b_ih_pr, const float* __restrict__ b_hh_pr,
                            const float* __restrict__ b_ih_bd, const float* __restrict__ b_hh_bd,
                            const float* __restrict__ w_ioux, const float* __restrict__ w_fx,
                            const float* __restrict__ w_hh_pf, const float* __restrict__ w_hh_pr,
                            const float* __restrict__ w_hh_bd)
{
    int i = blockIdx.x * 256 + threadIdx.x;
    if (i < 900)            g_biasx[i] = b_ioux[i] + b_iouh[i];
    else if (i < 1200)      g_biasx[i] = b_fx[i - 900];
    else if (i < 1800)      { int q = i - 1200; g_bias_pf[q] = b_ih_pf[q] + b_hh_pf[q]; }
    else if (i < 2400)      { int q = i - 1800; g_bias_pr[q] = b_ih_pr[q] + b_hh_pr[q]; }
    else if (i < 3000)      { int q = i - 2400; g_bias_bd[q] = b_ih_bd[q] + b_hh_bd[q]; }
    else if (i < 273000)    { int q = i - 3000;   g_wx[q] = w_ioux[q]; }
    else if (i < 363000)    { int q = i - 273000; g_wx[270000 + q] = w_fx[q]; }
    else if (i < 413000)    { int q = i - 363000; g_map[q] = -1; if (q == 0) g_cnt = 0; }
    else if (i < 504200)    { int q = i - 413000; int r = q / 152, k = q - r * 152;
                              g_whh_pf_p[q] = (k < 150) ? w_hh_pf[r * 150 + k] : 0.f; }
    else if (i < 595400)    { int q = i - 504200; int r = q / 152, k = q - r * 152;
                              g_whh_pr_p[q] = (k < 150) ? w_hh_pr[r * 150 + k] : 0.f; }
    else if (i < 686600)    { int q = i - 595400; int r = q / 152, k = q - r * 152;
                              g_whh_bd_p[q] = (k < 150) ? w_hh_bd[r * 150 + k] : 0.f; }
}

// ---------------- generic K=300 GEMM:  C[r,n] = sum_k A(r,k) * W[n,k] + bias[n] ----
// MODE 0 : A(r,k) = emb[g_utok[r]*300+k], rows = g_cnt (dynamic, early-exit)
// MODE 4 : A(r,k) = A[r*300+k]          (plain)
// MODE 5 : MERGED para x-gate launch: blockIdx.y>=8 -> reverse job.
// MODE 12: MERGED tree-level launch (iou | f sub-GEMMs by blockIdx.x).
//
// TENSOR-CORE core (R10 proven layout + R13 double buffering): 128x128 CTA
// tile, 8 warps in 2x4, split-TF32 mma.sync m16n8k8 (hi*hi+hi*lo+lo*hi).
// tf32 hi/lo PLANES, [row][k] stride 20 (conflict-free LDS.32). TWO full
// 16-K smem buffers in DYNAMIC smem: one __syncthreads per tile (store to
// buf^1 overlaps other warps' compute of buf) -> no per-tile pipeline drain.
template<int MODE>
__global__ void __launch_bounds__(256, 2) gemm300(
    const float* __restrict__ A, const float* __restrict__ W,
    const float* __restrict__ bias, float* __restrict__ C,
    int rows, int ncols,
    const float* __restrict__ W2, float* __restrict__ C2,
    int size, int offPrev, int rev)
{
    extern __shared__ __align__(16) float dynsm[];   // [2][4][GP]
    __shared__ int rbase[128];

    const int tid = threadIdx.x;

    bool m2 = false;
    int job = 0;
    int rowBase, colBase;
    const float* Wsel = W;
    float*       Csel = C;
    const float* biasE = bias;
    int ncolsE = ncols;
    int nrows;
    if (MODE == 12) {
        rowBase = blockIdx.y * 128;
        m2 = blockIdx.x >= 8;
        colBase = m2 ? (blockIdx.x - 8) * 128 : blockIdx.x * 128;
        Wsel = m2 ? W2 : W;
        Csel = m2 ? C2 : C;
        ncolsE = m2 ? MDIM : G3;
        nrows = m2 ? rows * 2 : rows;
    } else if (MODE == 5) {
        job = blockIdx.y >> 3;
        rowBase = (blockIdx.y & 7) * 128;
        colBase = blockIdx.x * 128;
        Wsel = job ? W2 : W;
        Csel = job ? g_xg_pr : g_xg_pf;
        biasE = job ? g_bias_pr : g_bias_pf;
        ncolsE = 600;
        nrows = 1024;
    } else {
        rowBase = blockIdx.y * 128;
        colBase = blockIdx.x * 128;
        nrows = (MODE == 0) ? g_cnt : rows;
    }
    if ((MODE == 0 || MODE == 12) && rowBase >= nrows) return;   // uniform per block

    if (tid < 128) {
        int r = rowBase + tid;
        int rb = -1;
        if (r < nrows) {
            if (MODE == 0)       { rb = g_utok[r] * 300; }
            else if (MODE == 12) {
                if (!m2) { int b = r / size; int kk = r - b * size;
                           rb = (b * NNODE + offPrev + 2 * kk) * MDIM; }
                else     { int s2 = size * 2; int b = r / s2; int rem = r - b * s2;
                           rb = (b * NNODE + offPrev + rem) * MDIM; }
            }
            else if (MODE == 5)  { int t = r >> 5, p = r & 31; int te = job ? 31 - t : t;
                                   rb = ((1 + p * 32 + te) * NNODE + 62) * MDIM; }
            else                 rb = r * 300;
        }
        rbase[tid] = rb;
    }
    __syncthreads();

    // loader mapping: 256 threads; each loads 2 A-rows and 2 W-rows, one float4 each
    const int lrow = tid >> 2;            // 0..63
    const int kq   = (tid & 3) * 4;       // k offset within 16-wide tile: 0,4,8,12
    const int arb0 = rbase[lrow];
    const int arb1 = rbase[lrow + 64];
    const int wr0  = colBase + lrow;
    const int wr1  = colBase + lrow + 64;
    const bool w0ok = wr0 < ncolsE;
    const bool w1ok = wr1 < ncolsE;
    const float* wp0 = Wsel + (size_t)(w0ok ? wr0 : 0) * 300;
    const float* wp1 = Wsel + (size_t)(w1ok ? wr1 : 0) * 300;

    // mma fragment mapping
    const int w    = tid >> 5, lane = tid & 31;
    const int g    = lane >> 2, t4 = lane & 3;
    const int wrr  = w & 1;               // 0..1 -> 64-row group
    const int wcc  = w >> 1;              // 0..3 -> 32-col group

    float c[4][4][4];                     // [mtile][ntile][reg], 64 accum regs
#pragma unroll
    for (int mt = 0; mt < 4; mt++)
#pragma unroll
        for (int nt = 0; nt < 4; nt++)
#pragma unroll
            for (int q = 0; q < 4; q++) c[mt][nt][q] = 0.f;

    float4 a0v, a1v, w0v, w1v;

    auto LOADT = [&](int k0) {
        const float4 Z = make_float4(0.f, 0.f, 0.f, 0.f);
        a0v = Z; a1v = Z; w0v = Z; w1v = Z;
        int k = k0 + kq;
        if (k < 300) {
            if (arb0 >= 0) {
                a0v = *(const float4*)(A + arb0 + k);
                if (MODE == 12 && !m2) {
                    float4 t2 = *(const float4*)(A + arb0 + 300 + k);
                    a0v.x += t2.x; a0v.y += t2.y; a0v.z += t2.z; a0v.w += t2.w;
                }
            }
            if (arb1 >= 0) {
                a1v = *(const float4*)(A + arb1 + k);
                if (MODE == 12 && !m2) {
                    float4 t2 = *(const float4*)(A + arb1 + 300 + k);
                    a1v.x += t2.x; a1v.y += t2.y; a1v.z += t2.z; a1v.w += t2.w;
                }
            }
            if (w0ok) w0v = *(const float4*)(wp0 + k);
            if (w1ok) w1v = *(const float4*)(wp1 + k);
        }
    };

    auto SPLIT4 = [&](float4 v, float* hp, float* lp) {
        float4 h, l;
        tf32_split(v.x, h.x, l.x); tf32_split(v.y, h.y, l.y);
        tf32_split(v.z, h.z, l.z); tf32_split(v.w, h.w, l.w);
        *(float4*)hp = h; *(float4*)lp = l;
    };

    LOADT(0);
    int buf = 0;
    for (int k0 = 0; k0 < 300; k0 += 16) {
        float* Ah = dynsm + buf * GBUF;
        float* Al = Ah + GP;
        float* Bh = Al + GP;
        float* Bl = Bh + GP;
        {   // STORET into the current buffer
            int s0 = lrow * 20 + kq;
            int s1 = (lrow + 64) * 20 + kq;
            SPLIT4(a0v, &Ah[s0], &Al[s0]);
            SPLIT4(a1v, &Ah[s1], &Al[s1]);
            SPLIT4(w0v, &Bh[s0], &Bl[s0]);
            SPLIT4(w1v, &Bh[s1], &Bl[s1]);
        }
        __syncthreads();                  // the ONLY barrier per tile
        if (k0 + 16 < 300) LOADT(k0 + 16);    // prefetch hidden under the MMAs
#pragma unroll
        for (int ks = 0; ks < 2; ks++) {
            const int kb = ks * 8;
            unsigned bh[4][2], bl[4][2];
#pragma unroll
            for (int nt = 0; nt < 4; nt++) {
                int cb = (wcc * 32 + nt * 8 + g) * 20 + kb + t4;
                bh[nt][0] = __float_as_uint(Bh[cb]);
                bh[nt][1] = __float_as_uint(Bh[cb + 4]);
                bl[nt][0] = __float_as_uint(Bl[cb]);
                bl[nt][1] = __float_as_uint(Bl[cb + 4]);
            }
#pragma unroll
            for (int mt = 0; mt < 4; mt++) {
                int rb0 = (wrr * 64 + mt * 16 + g) * 20 + kb + t4;
                int rb1 = rb0 + 8 * 20;
                unsigned ah[4] = { __float_as_uint(Ah[rb0]), __float_as_uint(Ah[rb1]),
                                   __float_as_uint(Ah[rb0 + 4]), __float_as_uint(Ah[rb1 + 4]) };
                unsigned al[4] = { __float_as_uint(Al[rb0]), __float_as_uint(Al[rb1]),
                                   __float_as_uint(Al[rb0 + 4]), __float_as_uint(Al[rb1 + 4]) };
#pragma unroll
                for (int nt = 0; nt < 4; nt++) {
                    mma_tf32(c[mt][nt], ah, bh[nt]);   // hi*hi
                    mma_tf32(c[mt][nt], ah, bl[nt]);   // hi*lo
                    mma_tf32(c[mt][nt], al, bh[nt]);   // lo*hi
                }
            }
        }
        buf ^= 1;
    }

    // epilogue: c regs -> D rows (g, g+8), cols (2t, 2t+1). ncolsE is even, col
    // even -> float2 store in-bounds iff col < ncolsE. 8B-aligned.
#pragma unroll
    for (int mt = 0; mt < 4; mt++) {
        int r0 = rowBase + wrr * 64 + mt * 16 + g;
        int r1 = r0 + 8;
#pragma unroll
        for (int nt = 0; nt < 4; nt++) {
            int col = colBase + wcc * 32 + nt * 8 + 2 * t4;
            if (col >= ncolsE) continue;
            float bx = 0.f, by = 0.f;
            if (biasE) { float2 bv = *(const float2*)(biasE + col); bx = bv.x; by = bv.y; }
            if (r0 < nrows) {
                float2 v = make_float2(c[mt][nt][0] + bx, c[mt][nt][1] + by);
                *(float2*)(Csel + (size_t)r0 * ncolsE + col) = v;
            }
            if (r1 < nrows) {
                float2 v = make_float2(c[mt][nt][2] + bx, c[mt][nt][3] + by);
                *(float2*)(Csel + (size_t)r1 * ncolsE + col) = v;
            }
        }
    }
}

// ---------------- tree level 0 (leaves), float4-vectorized -----------------
__global__ void __launch_bounds__(256) leaf_kernel_f4(int total)   // total = NB*32*75
{
    int e = blockIdx.x * 256 + threadIdx.x;
    if (e >= total) return;
    int n = e / 75, q = e - n * 75;       // node index, float4 chunk
    int b = n >> 5, leaf = n & 31;
    int pos = b * NNODE + leaf;
    const float4* xr = (const float4*)(g_xproj + (size_t)g_uid[pos] * NCX);
    float4 iv = xr[q], ov = xr[75 + q], uv = xr[150 + q];
    float4 cv, hv;
    { float i = sigmf(iv.x), o = sigmf(ov.x), u = tanhfast(uv.x);
      cv.x = i * u; hv.x = o * tanhfast(cv.x); }
    { float i = sigmf(iv.y), o = sigmf(ov.y), u = tanhfast(uv.y);
      cv.y = i * u; hv.y = o * tanhfast(cv.y); }
    { float i = sigmf(iv.z), o = sigmf(ov.z), u = tanhfast(uv.z);
      cv.z = i * u; hv.z = o * tanhfast(cv.z); }
    { float i = sigmf(iv.w), o = sigmf(ov.w), u = tanhfast(uv.w);
      cv.w = i * u; hv.w = o * tanhfast(cv.w); }
    ((float4*)g_c)[(size_t)pos * 75 + q] = cv;
    ((float4*)g_h)[(size_t)pos * 75 + q] = hv;
}

// ---------------- tree levels 1..5, float4-vectorized ----------------------
__global__ void __launch_bounds__(256) node_kernel_f4(
    int size, int off, int offPrev, const float* __restrict__ b_fh, int total)
{
    int e = blockIdx.x * 256 + threadIdx.x;
    if (e >= total) return;               // total = NB*size*75
    int n = e / 75, q = e - n * 75;       // n = b*size+kk == grow
    int b = n / size, kk = n - b * size;
    int node = off + kk;
    int pos = b * NNODE + node;
    const float4* xr  = (const float4*)(g_xproj + (size_t)g_uid[pos] * NCX);
    const float4* g1r = (const float4*)(g_g1 + (size_t)n * G3);
    const float4* g2r = (const float4*)(g_g2 + (size_t)n * (2 * MDIM));
    int ch = offPrev + 2 * kk;
    const float4* h0 = (const float4*)g_h + (size_t)(b * NNODE + ch) * 75;

    float4 iv = xr[q],       ovv = xr[75 + q],  uvv = xr[150 + q], fxv = xr[225 + q];
    float4 g1a = g1r[q],     g1b = g1r[75 + q], g1c = g1r[150 + q];
    float4 g2a = g2r[q],     g2b = g2r[75 + q];
    float4 bf  = ((const float4*)b_fh)[q];
    float4 h0v = h0[q],      h1v = h0[75 + q];

    float4 cv, hv;
    { float i = sigmf(iv.x + g1a.x), o = sigmf(ovv.x + g1b.x), u = tanhfast(uvv.x + g1c.x);
      float fx = fxv.x + bf.x;
      float f0 = sigmf(g2a.x + fx), f1 = sigmf(g2b.x + fx);
      cv.x = i * u + f0 * h0v.x + f1 * h1v.x; hv.x = o * tanhfast(cv.x); }
    { float i = sigmf(iv.y + g1a.y), o = sigmf(ovv.y + g1b.y), u = tanhfast(uvv.y + g1c.y);
      float fx = fxv.y + bf.y;
      float f0 = sigmf(g2a.y + fx), f1 = sigmf(g2b.y + fx);
      cv.y = i * u + f0 * h0v.y + f1 * h1v.y; hv.y = o * tanhfast(cv.y); }
    { float i = sigmf(iv.z + g1a.z), o = sigmf(ovv.z + g1b.z), u = tanhfast(uvv.z + g1c.z);
      float fx = fxv.z + bf.z;
      float f0 = sigmf(g2a.z + fx), f1 = sigmf(g2b.z + fx);
      cv.z = i * u + f0 * h0v.z + f1 * h1v.z; hv.z = o * tanhfast(cv.z); }
    { float i = sigmf(iv.w + g1a.w), o = sigmf(ovv.w + g1b.w), u = tanhfast(uvv.w + g1c.w);
      float fx = fxv.w + bf.w;
      float f0 = sigmf(g2a.w + fx), f1 = sigmf(g2b.w + fx);
      cv.w = i * u + f0 * h0v.w + f1 * h1v.w; hv.w = o * tanhfast(cv.w); }
    ((float4*)g_c)[(size_t)pos * 75 + q] = cv;
    ((float4*)g_h)[(size_t)pos * 75 + q] = hv;
}

// ---------------- paragraph bi-LSTM: ALL 32 steps in one launch ----------------
__global__ void para_all()
{
    int job = blockIdx.y;                // 0 = fwd, 1 = rev
    int pb = blockIdx.x * 4;
    const float* xg  = job ? g_xg_pr : g_xg_pf;
    const float* whp = job ? g_whh_pr_p : g_whh_pf_p;
    float* hs = g_ph + job * 32 * MEMD;
    float* cs = g_pc + job * 32 * MEMD;
    __shared__ __align__(16) float hsh[608];   // 4 regions x 152 (pads zeroed)
    __shared__ float gsh[2400];                // 4 x 600
    int j = threadIdx.x;                       // 600
    if (j < 8) { int r = j >> 1; hsh[r * 152 + 150 + (j & 1)] = 0.f; }
    const float4* wr4 = (const float4*)(whp + (size_t)j * 152);
    for (int t = 0; t < 32; t++) {
        if (t > 0) { int pp = j / MEMD, m = j % MEMD;
                     hsh[pp * 152 + m] = hs[(pb + pp) * MEMD + m]; }
        __syncthreads();

        int xb = ((t << 5) + pb) * 600 + j;
        float a0 = xg[xb], a1 = xg[xb + 600], a2 = xg[xb + 1200], a3 = xg[xb + 1800];
        if (t > 0) {
#pragma unroll 19
            for (int k4 = 0; k4 < 38; k4++) {
                float4 w  = wr4[k4];
                float4 h0 = *(const float4*)&hsh[k4 * 4];
                float4 h1 = *(const float4*)&hsh[152 + k4 * 4];
                float4 h2 = *(const float4*)&hsh[304 + k4 * 4];
                float4 h3 = *(const float4*)&hsh[456 + k4 * 4];
                a0 += w.x * h0.x + w.y * h0.y + w.z * h0.z + w.w * h0.w;
                a1 += w.x * h1.x + w.y * h1.y + w.z * h1.z + w.w * h1.w;
                a2 += w.x * h2.x + w.y * h2.y + w.z * h2.z + w.w * h2.w;
                a3 += w.x * h3.x + w.y * h3.y + w.z * h3.z + w.w * h3.w;
            }
        }
        gsh[j] = a0; gsh[600 + j] = a1; gsh[1200 + j] = a2; gsh[1800 + j] = a3;
        __syncthreads();

        int pp = j / MEMD, m = j % MEMD;
        int p = pb + pp;
        const float* gp = gsh + pp * 600;
        float gi = gp[m], gf = gp[150 + m], gg = gp[300 + m], go = gp[450 + m];
        float cprev = (t > 0) ? cs[p * MEMD + m] : 0.f;
        float c2 = sigmf(gf) * cprev + sigmf(gi) * tanhfast(gg);
        float h2 = sigmf(go) * tanhfast(c2);
        cs[p * MEMD + m] = c2;
        hs[p * MEMD + m] = h2;
        if (t == 31) g_phidden[p * MDIM + job * MEMD + m] = h2;
        __syncthreads();                 // h/c writes visible before next t's hsh load
    }
}

// ---------------- body LSTM scan (upstream quirk: bwd cell uses fresh fwd h) ---
__global__ void body_scan()
{
    __shared__ __align__(16) float hf[152];
    __shared__ float cf[MEMD], cb[MEMD], g[600];
    int j = threadIdx.x;                 // 600
    if (j < 2) hf[150 + j] = 0.f;        // pad
    const float4* wr4 = (const float4*)(g_whh_bd_p + (size_t)j * 152);
    __syncthreads();
    for (int t = 0; t < 32; t++) {
        float acc = g_xg_bd[t * 600 + j];
        if (t > 0) {
#pragma unroll 19
            for (int k4 = 0; k4 < 38; k4++) {
                float4 w = wr4[k4];
                float4 h = *(const float4*)&hf[k4 * 4];
                acc += w.x * h.x + w.y * h.y + w.z * h.z + w.w * h.w;
            }
        }
        g[j] = acc;
        __syncthreads();
        if (j < MEMD) {
            float cprev = (t > 0) ? cf[j] : 0.f;
            float c2 = sigmf(g[150 + j]) * cprev + sigmf(g[j]) * tanhfast(g[300 + j]);
            float h2 = sigmf(g[450 + j]) * tanhfast(c2);
            cf[j] = c2; hf[j] = h2;
            g_hbody[t * MDIM + j] = h2;
        }
        __syncthreads();
        float acc2 = g_xg_bd[(31 - t) * 600 + j];
        {
#pragma unroll 19
            for (int k4 = 0; k4 < 38; k4++) {
                float4 w = wr4[k4];
                float4 h = *(const float4*)&hf[k4 * 4];   // hf == fresh h_f2
                acc2 += w.x * h.x + w.y * h.y + w.z * h.z + w.w * h.w;
            }
        }
        g[j] = acc2;
        __syncthreads();
        if (j < MEMD) {
            float cprev = (t > 0) ? cb[j] : 0.f;
            float c2 = sigmf(g[150 + j]) * cprev + sigmf(g[j]) * tanhfast(g[300 + j]);
            float h2 = sigmf(g[450 + j]) * tanhfast(c2);
            cb[j] = c2;
            g_hbody[t * MDIM + 150 + j] = h2;
        }
        __syncthreads();
    }
}

// ---------------- gating: logits[p,m] = w_sel[m,:] . [h_body[p] ; para_rep] ----
__global__ void gate_logits(const float* __restrict__ w_sel, const float* __restrict__ b_sel)
{
    int p = blockIdx.x;
    int m = threadIdx.x;                 // 300
    __shared__ __align__(16) float gi[600];
    gi[m]       = g_hbody[p * MDIM + m];
    gi[300 + m] = g_hbody[31 * MDIM + m];  // para_rep == h_body[31]
    __syncthreads();
    float acc = b_sel[m];
    const float4* wr4 = (const float4*)(w_sel + (size_t)m * 600);
    const float4* gi4 = (const float4*)gi;
#pragma unroll 10
    for (int q4 = 0; q4 < 150; q4++) {
        float4 w = wr4[q4], v = gi4[q4];
        acc += w.x * v.x + w.y * v.y + w.z * v.z + w.w * v.w;
    }
    g_gatel[p * MDIM + m] = acc;
}

// softmax over features per row, weighted sum over rows; also emit rhidden ------
__global__ void finalize(float* __restrict__ out)
{
    int tid = threadIdx.x;               // 512
    __shared__ float red[512];
    float acc = 0.f;
    for (int p = 0; p < 32; p++) {
        float v = (tid < 300) ? g_gatel[p * MDIM + tid] : -3.0e38f;
        red[tid] = v; __syncthreads();
        for (int s = 256; s > 0; s >>= 1) {
            if (tid < s) red[tid] = fmaxf(red[tid], red[tid + s]);
            __syncthreads();
        }
        float mx = red[0]; __syncthreads();
        float e = (tid < 300) ? __expf(v - mx) : 0.f;
        red[tid] = e; __syncthreads();
        for (int s = 256; s > 0; s >>= 1) {
            if (tid < s) red[tid] += red[tid + s];
            __syncthreads();
        }
        float sm = red[0]; __syncthreads();
        if (tid < 300) acc += g_hbody[p * MDIM + tid] * __fdividef(e, sm);
    }
    if (tid < 300) {
        out[tid] = acc;                                    // h_body_prime
        out[300 + tid] = g_c[62 * MDIM + tid];             // rhidden = root c of head (b=0)
    }
}

// ---------------- launch ----------------
extern "C" void kernel_launch(void* const* d_in, const int* in_sizes, int n_in,
                              void* d_out, int out_size)
{
    const float* emb     = (const float*)d_in[0];
    const int*   headt   = (const int*)d_in[1];
    const int*   bodyt   = (const int*)d_in[2];
    const float* w_ioux  = (const float*)d_in[3];
    const float* b_ioux  = (const float*)d_in[4];
    const float* w_iouh  = (const float*)d_in[5];
    const float* b_iouh  = (const float*)d_in[6];
    const float* w_fx    = (const float*)d_in[7];
    const float* b_fx    = (const float*)d_in[8];
    const float* w_fh    = (const float*)d_in[9];
    const float* b_fh    = (const float*)d_in[10];
    const float* w_ih_pf = (const float*)d_in[11];
    const float* w_hh_pf = (const float*)d_in[12];
    const float* b_ih_pf = (const float*)d_in[13];
    const float* b_hh_pf = (const float*)d_in[14];
    const float* w_ih_pr = (const float*)d_in[15];
    const float* w_hh_pr = (const float*)d_in[16];
    const float* b_ih_pr = (const float*)d_in[17];
    const float* b_hh_pr = (const float*)d_in[18];
    const float* w_ih_bd = (const float*)d_in[19];
    const float* w_hh_bd = (const float*)d_in[20];
    const float* b_ih_bd = (const float*)d_in[21];
    const float* b_hh_bd = (const float*)d_in[22];
    const float* w_sel   = (const float*)d_in[23];
    const float* b_sel   = (const float*)d_in[24];
    float* out = (float*)d_out;

    float *p_xproj, *p_c, *p_g1, *p_g2, *p_wx, *p_biasx, *p_bbd, *p_xgbd, *p_phid;
    cudaGetSymbolAddress((void**)&p_xproj, g_xproj);
    cudaGetSymbolAddress((void**)&p_c,     g_c);
    cudaGetSymbolAddress((void**)&p_g1,    g_g1);
    cudaGetSymbolAddress((void**)&p_g2,    g_g2);
    cudaGetSymbolAddress((void**)&p_wx,    g_wx);
    cudaGetSymbolAddress((void**)&p_biasx, g_biasx);
    cudaGetSymbolAddress((void**)&p_bbd,   g_bias_bd);
    cudaGetSymbolAddress((void**)&p_xgbd,  g_xg_bd);
    cudaGetSymbolAddress((void**)&p_phid,  g_phidden);

    // allow 80KB dynamic smem on all gemm instantiations (immediate API; capture-safe)
    cudaFuncSetAttribute(gemm300<0>,  cudaFuncAttributeMaxDynamicSharedMemorySize, GEMM_DYN_BYTES);
    cudaFuncSetAttribute(gemm300<4>,  cudaFuncAttributeMaxDynamicSharedMemorySize, GEMM_DYN_BYTES);
    cudaFuncSetAttribute(gemm300<5>,  cudaFuncAttributeMaxDynamicSharedMemorySize, GEMM_DYN_BYTES);
    cudaFuncSetAttribute(gemm300<12>, cudaFuncAttributeMaxDynamicSharedMemorySize, GEMM_DYN_BYTES);

    // 1. prep (biases + x-weight + dedup map init + padded whh)
    prep_kernel<<<(686600 + 255) / 256, 256>>>(b_ioux, b_iouh, b_fx,
                                               b_ih_pf, b_hh_pf, b_ih_pr, b_hh_pr,
                                               b_ih_bd, b_hh_bd, w_ioux, w_fx,
                                               w_hh_pf, w_hh_pr, w_hh_bd);

    // 2-3. dedup claim + assign
    dedup_claim<<<(NROWS + 255) / 256, 256>>>(headt, bodyt);
    dedup_assign<<<(NROWS + 255) / 256, 256>>>(headt, bodyt);

    // 4. x-projection GEMM over UNIQUE tokens (launch #4 -> ncu capture slot)
    gemm300<0><<<dim3(10, (VOCAB + 127) / 128), 256, GEMM_DYN_BYTES>>>(
        emb, p_wx, p_biasx, p_xproj, VOCAB, NCX, nullptr, nullptr, 0, 0, 0);

    // 5. row -> unique-id gather (only needed by leaf/node)
    dedup_gather<<<(NROWS + 255) / 256, 256>>>(headt, bodyt);

    // 6. tree level 0 (leaves)
    {
        int total = NB * 32 * 75;
        leaf_kernel_f4<<<(total + 255) / 256, 256>>>(total);
    }

    // 7. tree levels 1..5: ONE merged GEMM launch (iou + f) + node combine
    const int sizes[5] = {16, 8, 4, 2, 1};
    const int offs[5]  = {32, 48, 56, 60, 62};
    const int offp[5]  = {0, 32, 48, 56, 60};
    for (int l = 0; l < 5; l++) {
        int sz = sizes[l];
        int rows1 = NB * sz, rows2 = rows1 * 2;
        gemm300<12><<<dim3(11, (rows2 + 127) / 128), 256, GEMM_DYN_BYTES>>>(
            p_c, w_iouh, nullptr, p_g1, rows1, 0, w_fh, p_g2, sz, offp[l], 0);
        int total = rows1 * 75;
        node_kernel_f4<<<(total + 255) / 256, 256>>>(sz, offs[l], offp[l], b_fh, total);
    }

    // 8. paragraph LSTM x-gates, fwd + rev in ONE launch (MODE 5)
    gemm300<5><<<dim3(5, 16), 256, GEMM_DYN_BYTES>>>(
        p_c, w_ih_pf, nullptr, nullptr, 1024, 600, w_ih_pr, nullptr, 0, 0, 0);

    // 9. paragraph bi-LSTM recurrence: single fused launch (block-local chains)
    para_all<<<dim3(8, 2), 600>>>();

    // 10. body LSTM x-gates + scan
    gemm300<4><<<dim3(5, 1), 256, GEMM_DYN_BYTES>>>(
        p_phid, w_ih_bd, p_bbd, p_xgbd, 32, 600, nullptr, nullptr, 0, 0, 0);
    body_scan<<<1, 600>>>();

    // 11. selective gating + outputs
    gate_logits<<<32, 300>>>(w_sel, b_sel);
    finalize<<<1, 512>>>(out);
}